// round 1
// baseline (speedup 1.0000x reference)
#include <cuda_runtime.h>
#include <math.h>

// ---------------------------------------------------------------------------
// Problem constants
// ---------------------------------------------------------------------------
#define R_ROIS 2048
#define CCH    512
#define HWDIM  64
#define DDIM   4096
#define NCLS   21
#define KHALF  2048    // SPP produces 2048 unique features, duplicated to 4096

// Output layout in d_out (fp32):
//   [0, 43008)        dm  [2048, 21]
//   [43008, 86016)    dr  [2048, 21]
//   [86016, 86037)    score [21]
#define OUT_DM 0
#define OUT_DR (R_ROIS * NCLS)
#define OUT_SC (2 * R_ROIS * NCLS)

// ---------------------------------------------------------------------------
// Scratch (device globals; no allocation allowed)
// ---------------------------------------------------------------------------
__device__ float g_y[R_ROIS * KHALF];       // SPP output (unique half)   16.8 MB
__device__ float g_wsum6[DDIM * KHALF];     // w6[:, :2048] + w6[:, 2048:] 33.6 MB
__device__ float g_h1[R_ROIS * DDIM];       // FC6 output                 33.6 MB
__device__ float g_h2[R_ROIS * DDIM];       // FC7 output                 33.6 MB
__device__ float g_xc[R_ROIS * NCLS];
__device__ float g_xd[R_ROIS * NCLS];
__device__ float g_colmax[NCLS];
__device__ float g_colsum[NCLS];

// ---------------------------------------------------------------------------
// SPP: per-ROI 14x14 crop, 7x7/stride-7 max pool -> [C, 2, 2] -> y[r, c*4+q]
// One block per ROI, one warp per channel (strided).
// ---------------------------------------------------------------------------
__global__ __launch_bounds__(256) void spp_kernel(const float* __restrict__ x,
                                                  const int* __restrict__ ssw) {
    int r = blockIdx.x;
    int y0 = ssw[r * 4 + 0];
    int x0 = ssw[r * 4 + 1];
    int warp = threadIdx.x >> 5;
    int lane = threadIdx.x & 31;

    const float* base0 = x + y0 * HWDIM + x0;
    for (int c = warp; c < CCH; c += 8) {
        const float* base = base0 + c * (HWDIM * HWDIM);
        float m0 = -INFINITY, m1 = -INFINITY, m2 = -INFINITY, m3 = -INFINITY;
#pragma unroll
        for (int k = 0; k < 7; k++) {
            int p = lane + k * 32;
            if (p < 196) {
                int i = p / 14;
                int j = p - i * 14;
                float v = base[i * HWDIM + j];
                bool bi = (i >= 7), bj = (j >= 7);
                if (!bi) { if (!bj) m0 = fmaxf(m0, v); else m1 = fmaxf(m1, v); }
                else     { if (!bj) m2 = fmaxf(m2, v); else m3 = fmaxf(m3, v); }
            }
        }
#pragma unroll
        for (int o = 16; o; o >>= 1) {
            m0 = fmaxf(m0, __shfl_xor_sync(0xFFFFFFFFu, m0, o));
            m1 = fmaxf(m1, __shfl_xor_sync(0xFFFFFFFFu, m1, o));
            m2 = fmaxf(m2, __shfl_xor_sync(0xFFFFFFFFu, m2, o));
            m3 = fmaxf(m3, __shfl_xor_sync(0xFFFFFFFFu, m3, o));
        }
        if (lane == 0) {
            float4 out = make_float4(m0, m1, m2, m3);
            *reinterpret_cast<float4*>(&g_y[r * KHALF + c * 4]) = out;
        }
    }
}

// ---------------------------------------------------------------------------
// wsum6[e,k] = w6[e,k] + w6[e,k+2048]   (exploits duplicated SPP features)
// ---------------------------------------------------------------------------
__global__ __launch_bounds__(256) void wsum_kernel(const float* __restrict__ w6) {
    int t = blockIdx.x * blockDim.x + threadIdx.x;     // float4 index
    const int NQ = DDIM * KHALF / 4;                   // 2,097,152
    if (t >= NQ) return;
    int e = t / (KHALF / 4);
    int kq = t - e * (KHALF / 4);
    const float4* a = reinterpret_cast<const float4*>(w6 + (long)e * DDIM) + kq;
    const float4* b = reinterpret_cast<const float4*>(w6 + (long)e * DDIM + KHALF) + kq;
    float4 av = *a, bv = *b;
    float4 o = make_float4(av.x + bv.x, av.y + bv.y, av.z + bv.z, av.w + bv.w);
    reinterpret_cast<float4*>(g_wsum6 + (long)e * KHALF)[kq] = o;
}

// ---------------------------------------------------------------------------
// C[m,n] = relu(bias[n] + sum_k A[m,k] * B[n,k])   (NT GEMM, fp32)
// 128x128 block tile, BK=16, 8x8 per-thread register tile, 256 threads.
// ---------------------------------------------------------------------------
#define BM 128
#define BN 128
#define BK 16

__global__ __launch_bounds__(256) void gemm_bias_relu(
    const float* __restrict__ A, const float* __restrict__ B,
    const float* __restrict__ bias, float* __restrict__ C,
    int M, int N, int K) {
    __shared__ float As[BK][BM + 4];
    __shared__ float Bs[BK][BN + 4];

    int tid = threadIdx.x;
    int bm0 = blockIdx.y * BM;
    int bn0 = blockIdx.x * BN;
    int tx = tid & 15;         // 0..15 -> N
    int ty = tid >> 4;         // 0..15 -> M

    const float* Aptr = A + (long)bm0 * K;
    const float* Bptr = B + (long)bn0 * K;

    float acc[8][8];
#pragma unroll
    for (int i = 0; i < 8; i++)
#pragma unroll
        for (int j = 0; j < 8; j++) acc[i][j] = 0.f;

    for (int k0 = 0; k0 < K; k0 += BK) {
#pragma unroll
        for (int t = 0; t < 2; t++) {
            int f = tid + t * 256;         // 0..511 float4 slots
            int row = f >> 2;              // 0..127
            int kq = (f & 3) * 4;          // 0,4,8,12
            float4 av = *reinterpret_cast<const float4*>(Aptr + (long)row * K + k0 + kq);
            As[kq + 0][row] = av.x; As[kq + 1][row] = av.y;
            As[kq + 2][row] = av.z; As[kq + 3][row] = av.w;
            float4 bv = *reinterpret_cast<const float4*>(Bptr + (long)row * K + k0 + kq);
            Bs[kq + 0][row] = bv.x; Bs[kq + 1][row] = bv.y;
            Bs[kq + 2][row] = bv.z; Bs[kq + 3][row] = bv.w;
        }
        __syncthreads();

#pragma unroll
        for (int kk = 0; kk < BK; kk++) {
            float a[8], b[8];
            *reinterpret_cast<float4*>(a)     = *reinterpret_cast<const float4*>(&As[kk][ty * 8]);
            *reinterpret_cast<float4*>(a + 4) = *reinterpret_cast<const float4*>(&As[kk][ty * 8 + 4]);
            *reinterpret_cast<float4*>(b)     = *reinterpret_cast<const float4*>(&Bs[kk][tx * 8]);
            *reinterpret_cast<float4*>(b + 4) = *reinterpret_cast<const float4*>(&Bs[kk][tx * 8 + 4]);
#pragma unroll
            for (int i = 0; i < 8; i++)
#pragma unroll
                for (int j = 0; j < 8; j++) acc[i][j] = fmaf(a[i], b[j], acc[i][j]);
        }
        __syncthreads();
    }

#pragma unroll
    for (int i = 0; i < 8; i++) {
        int row = bm0 + ty * 8 + i;
#pragma unroll
        for (int j = 0; j < 8; j++) {
            int col = bn0 + tx * 8 + j;
            float v = acc[i][j] + bias[col];
            C[(long)row * N + col] = fmaxf(v, 0.f);
        }
    }
}

// ---------------------------------------------------------------------------
// Heads: xc[r,c] = relu(h2[r,:]·w8c[c,:] + b8c[c]); same for xd with w8d.
// One block per ROI; h2 row staged in smem; warp-per-output dot products.
// ---------------------------------------------------------------------------
__global__ __launch_bounds__(256) void heads_kernel(
    const float* __restrict__ w8c, const float* __restrict__ b8c,
    const float* __restrict__ w8d, const float* __restrict__ b8d) {
    __shared__ float hs[DDIM];
    int r = blockIdx.x;
    const float* hrow = g_h2 + (long)r * DDIM;
    for (int i = threadIdx.x; i < DDIM / 4; i += 256)
        reinterpret_cast<float4*>(hs)[i] = reinterpret_cast<const float4*>(hrow)[i];
    __syncthreads();

    int warp = threadIdx.x >> 5;
    int lane = threadIdx.x & 31;
    for (int o = warp; o < 2 * NCLS; o += 8) {
        int c = (o < NCLS) ? o : (o - NCLS);
        const float* wrow = ((o < NCLS) ? w8c : w8d) + (long)c * DDIM;
        float s = 0.f;
        for (int k4 = lane; k4 < DDIM / 4; k4 += 32) {
            float4 hv = reinterpret_cast<const float4*>(hs)[k4];
            float4 wv = reinterpret_cast<const float4*>(wrow)[k4];
            s += hv.x * wv.x + hv.y * wv.y + hv.z * wv.z + hv.w * wv.w;
        }
#pragma unroll
        for (int off = 16; off; off >>= 1) s += __shfl_xor_sync(0xFFFFFFFFu, s, off);
        if (lane == 0) {
            float b = (o < NCLS) ? b8c[c] : b8d[c];
            float v = fmaxf(s + b, 0.f);
            if (o < NCLS) g_xc[r * NCLS + c] = v;
            else          g_xd[r * NCLS + c] = v;
        }
    }
}

// ---------------------------------------------------------------------------
// Column stats for softmax over ROIs (axis=1): per class, max and sum(exp).
// ---------------------------------------------------------------------------
__global__ __launch_bounds__(256) void colstats_kernel() {
    __shared__ float red[256];
    int c = blockIdx.x;
    int t = threadIdx.x;
    float m = -INFINITY;
    for (int r = t; r < R_ROIS; r += 256) m = fmaxf(m, g_xd[r * NCLS + c]);
    red[t] = m;
    __syncthreads();
    for (int s = 128; s; s >>= 1) {
        if (t < s) red[t] = fmaxf(red[t], red[t + s]);
        __syncthreads();
    }
    float cm = red[0];
    __syncthreads();
    float s2 = 0.f;
    for (int r = t; r < R_ROIS; r += 256) s2 += expf(g_xd[r * NCLS + c] - cm);
    red[t] = s2;
    __syncthreads();
    for (int s = 128; s; s >>= 1) {
        if (t < s) red[t] += red[t + s];
        __syncthreads();
    }
    if (t == 0) { g_colmax[c] = cm; g_colsum[c] = red[0]; }
}

// ---------------------------------------------------------------------------
// Finalize: per ROI -> dr (softmax over classes), dm = dr * softmax_roi(xd).
// One warp per ROI; lanes 0..20 carry classes.
// ---------------------------------------------------------------------------
__global__ __launch_bounds__(256) void finalize_kernel(float* __restrict__ out) {
    int warp = threadIdx.x >> 5;
    int lane = threadIdx.x & 31;
    int r = blockIdx.x * 8 + warp;
    if (r >= R_ROIS) return;

    float v = (lane < NCLS) ? g_xc[r * NCLS + lane] : -INFINITY;
    float m = v;
#pragma unroll
    for (int off = 16; off; off >>= 1) m = fmaxf(m, __shfl_xor_sync(0xFFFFFFFFu, m, off));
    float e = (lane < NCLS) ? expf(v - m) : 0.f;
    float s = e;
#pragma unroll
    for (int off = 16; off; off >>= 1) s += __shfl_xor_sync(0xFFFFFFFFu, s, off);

    if (lane < NCLS) {
        float dr = e / s;
        float smd = expf(g_xd[r * NCLS + lane] - g_colmax[lane]) / g_colsum[lane];
        float dm = dr * smd;
        out[OUT_DM + r * NCLS + lane] = dm;
        out[OUT_DR + r * NCLS + lane] = dr;
    }
}

// ---------------------------------------------------------------------------
// Score: deterministic tree-sum of dm over ROIs per class.
// ---------------------------------------------------------------------------
__global__ __launch_bounds__(256) void score_kernel(const float* __restrict__ dm,
                                                    float* __restrict__ score) {
    __shared__ float red[256];
    int c = blockIdx.x;
    int t = threadIdx.x;
    float s = 0.f;
    for (int r = t; r < R_ROIS; r += 256) s += dm[r * NCLS + c];
    red[t] = s;
    __syncthreads();
    for (int st = 128; st; st >>= 1) {
        if (t < st) red[t] += red[t + st];
        __syncthreads();
    }
    if (t == 0) score[c] = red[0];
}

// ---------------------------------------------------------------------------
// Launch
// ---------------------------------------------------------------------------
extern "C" void kernel_launch(void* const* d_in, const int* in_sizes, int n_in,
                              void* d_out, int out_size) {
    const float* x   = (const float*)d_in[0];
    const float* w6  = (const float*)d_in[1];
    const float* b6  = (const float*)d_in[2];
    const float* w7  = (const float*)d_in[3];
    const float* b7  = (const float*)d_in[4];
    const float* w8c = (const float*)d_in[5];
    const float* b8c = (const float*)d_in[6];
    const float* w8d = (const float*)d_in[7];
    const float* b8d = (const float*)d_in[8];
    const int*   ssw = (const int*)d_in[9];
    float* out = (float*)d_out;

    float *p_y, *p_wsum6, *p_h1, *p_h2;
    cudaGetSymbolAddress((void**)&p_y, g_y);
    cudaGetSymbolAddress((void**)&p_wsum6, g_wsum6);
    cudaGetSymbolAddress((void**)&p_h1, g_h1);
    cudaGetSymbolAddress((void**)&p_h2, g_h2);

    // 1) SPP
    spp_kernel<<<R_ROIS, 256>>>(x, ssw);

    // 2) Fold duplicated FC6 input halves: wsum6 = w6[:, :2048] + w6[:, 2048:]
    {
        int nq = DDIM * KHALF / 4;
        wsum_kernel<<<(nq + 255) / 256, 256>>>(w6);
    }

    // 3) FC6: h1 = relu(y · wsum6^T + b6)   M=2048 N=4096 K=2048
    {
        dim3 grid(DDIM / BN, R_ROIS / BM);
        gemm_bias_relu<<<grid, 256>>>(p_y, p_wsum6, b6, p_h1, R_ROIS, DDIM, KHALF);
    }

    // 4) FC7: h2 = relu(h1 · w7^T + b7)     M=2048 N=4096 K=4096
    {
        dim3 grid(DDIM / BN, R_ROIS / BM);
        gemm_bias_relu<<<grid, 256>>>(p_h1, w7, b7, p_h2, R_ROIS, DDIM, DDIM);
    }

    // 5) Classification / detection heads
    heads_kernel<<<R_ROIS, 256>>>(w8c, b8c, w8d, b8d);

    // 6) Softmax over ROIs: column stats
    colstats_kernel<<<NCLS, 256>>>();

    // 7) dr, dm
    finalize_kernel<<<R_ROIS / 8, 256>>>(out);

    // 8) score (deterministic reduction)
    score_kernel<<<NCLS, 256>>>(out + OUT_DM, out + OUT_SC);
}

// round 3
// speedup vs baseline: 2.4854x; 2.4854x over previous
#include <cuda_runtime.h>
#include <cuda_bf16.h>
#include <math.h>
#include <stdint.h>

// ---------------------------------------------------------------------------
// Problem constants
// ---------------------------------------------------------------------------
#define R_ROIS 2048
#define CCH    512
#define HWDIM  64
#define DDIM   4096
#define NCLS   21
#define KHALF  2048

#define OUT_DM 0
#define OUT_DR (R_ROIS * NCLS)
#define OUT_SC (2 * R_ROIS * NCLS)

// ---------------------------------------------------------------------------
// Scratch (device globals)
// ---------------------------------------------------------------------------
__device__ __nv_bfloat16 g_yh[R_ROIS * KHALF];
__device__ __nv_bfloat16 g_yl[R_ROIS * KHALF];
__device__ __nv_bfloat16 g_w6h[DDIM * KHALF];
__device__ __nv_bfloat16 g_w6l[DDIM * KHALF];
__device__ __nv_bfloat16 g_w7h[DDIM * DDIM];
__device__ __nv_bfloat16 g_w7l[DDIM * DDIM];
__device__ __nv_bfloat16 g_h1h[R_ROIS * DDIM];
__device__ __nv_bfloat16 g_h1l[R_ROIS * DDIM];
__device__ float g_h2[R_ROIS * DDIM];
__device__ float g_hpart[8 * R_ROIS * 48];
__device__ float g_xc[R_ROIS * NCLS];
__device__ float g_xd[R_ROIS * NCLS];
__device__ float g_colmax[NCLS];
__device__ float g_colsum[NCLS];

// ---------------------------------------------------------------------------
// Small helpers
// ---------------------------------------------------------------------------
__device__ __forceinline__ uint32_t smem_u32(const void* p) {
    uint32_t a;
    asm("{ .reg .u64 t; cvta.to.shared.u64 t, %1; cvt.u32.u64 %0, t; }" : "=r"(a) : "l"(p));
    return a;
}

__device__ __forceinline__ void split2(float v, __nv_bfloat16& h, __nv_bfloat16& l) {
    h = __float2bfloat16_rn(v);
    l = __float2bfloat16_rn(v - __bfloat162float(h));
}

// swizzled byte offset inside a [rows x 64 bf16] (128 B/row) SW128 tile
__device__ __forceinline__ uint32_t swz(int r, int g) {
    return (uint32_t)(r >> 3) * 1024u + (uint32_t)(r & 7) * 128u
         + (uint32_t)((g ^ (r & 7)) << 4);
}

#define CP_ASYNC16(dst, src) \
    asm volatile("cp.async.cg.shared.global [%0], [%1], 16;" :: "r"(dst), "l"(src))
#define CP_COMMIT() asm volatile("cp.async.commit_group;" ::: "memory")
#define CP_WAIT1()  asm volatile("cp.async.wait_group 1;" ::: "memory")

#define LDSM_X4(r0, r1, r2, r3, addr) \
    asm volatile("ldmatrix.sync.aligned.m8n8.x4.shared.b16 {%0,%1,%2,%3}, [%4];" \
                 : "=r"(r0), "=r"(r1), "=r"(r2), "=r"(r3) : "r"(addr))

#define MMA_BF16(c, a0, a1, a2, a3, b0, b1) \
    asm volatile("mma.sync.aligned.m16n8k16.row.col.f32.bf16.bf16.f32 " \
                 "{%0,%1,%2,%3}, {%4,%5,%6,%7}, {%8,%9}, {%0,%1,%2,%3};" \
                 : "+f"((c)[0]), "+f"((c)[1]), "+f"((c)[2]), "+f"((c)[3]) \
                 : "r"(a0), "r"(a1), "r"(a2), "r"(a3), "r"(b0), "r"(b1))

// ---------------------------------------------------------------------------
// SPP: per-ROI 14x14 crop, 7x7/stride-7 max pool -> bf16 hi/lo
// ---------------------------------------------------------------------------
__global__ __launch_bounds__(256) void spp_kernel(const float* __restrict__ x,
                                                  const int* __restrict__ ssw) {
    int r = blockIdx.x;
    int y0 = ssw[r * 4 + 0];
    int x0 = ssw[r * 4 + 1];
    int warp = threadIdx.x >> 5;
    int lane = threadIdx.x & 31;

    const float* base0 = x + y0 * HWDIM + x0;
    for (int c = warp; c < CCH; c += 8) {
        const float* base = base0 + c * (HWDIM * HWDIM);
        float m0 = -INFINITY, m1 = -INFINITY, m2 = -INFINITY, m3 = -INFINITY;
#pragma unroll
        for (int k = 0; k < 7; k++) {
            int p = lane + k * 32;
            if (p < 196) {
                int i = p / 14;
                int j = p - i * 14;
                float v = base[i * HWDIM + j];
                bool bi = (i >= 7), bj = (j >= 7);
                if (!bi) { if (!bj) m0 = fmaxf(m0, v); else m1 = fmaxf(m1, v); }
                else     { if (!bj) m2 = fmaxf(m2, v); else m3 = fmaxf(m3, v); }
            }
        }
#pragma unroll
        for (int o = 16; o; o >>= 1) {
            m0 = fmaxf(m0, __shfl_xor_sync(0xFFFFFFFFu, m0, o));
            m1 = fmaxf(m1, __shfl_xor_sync(0xFFFFFFFFu, m1, o));
            m2 = fmaxf(m2, __shfl_xor_sync(0xFFFFFFFFu, m2, o));
            m3 = fmaxf(m3, __shfl_xor_sync(0xFFFFFFFFu, m3, o));
        }
        if (lane == 0) {
            float v[4] = {m0, m1, m2, m3};
            __nv_bfloat16 hv[4], lv[4];
#pragma unroll
            for (int q = 0; q < 4; q++) split2(v[q], hv[q], lv[q]);
            *reinterpret_cast<uint2*>(&g_yh[r * KHALF + c * 4]) = *reinterpret_cast<uint2*>(hv);
            *reinterpret_cast<uint2*>(&g_yl[r * KHALF + c * 4]) = *reinterpret_cast<uint2*>(lv);
        }
    }
}

// ---------------------------------------------------------------------------
// wsum6[e,k] = w6[e,k] + w6[e,k+2048], split into bf16 hi/lo
// ---------------------------------------------------------------------------
__global__ __launch_bounds__(256) void wsum_split_kernel(const float* __restrict__ w6) {
    int t = blockIdx.x * blockDim.x + threadIdx.x;
    const int NQ = DDIM * KHALF / 4;
    if (t >= NQ) return;
    int e = t / (KHALF / 4);
    int kq = t - e * (KHALF / 4);
    float4 av = reinterpret_cast<const float4*>(w6 + (size_t)e * DDIM)[kq];
    float4 bv = reinterpret_cast<const float4*>(w6 + (size_t)e * DDIM + KHALF)[kq];
    float s[4] = {av.x + bv.x, av.y + bv.y, av.z + bv.z, av.w + bv.w};
    __nv_bfloat16 hv[4], lv[4];
#pragma unroll
    for (int q = 0; q < 4; q++) split2(s[q], hv[q], lv[q]);
    size_t idx = (size_t)e * KHALF + kq * 4;
    *reinterpret_cast<uint2*>(&g_w6h[idx]) = *reinterpret_cast<uint2*>(hv);
    *reinterpret_cast<uint2*>(&g_w6l[idx]) = *reinterpret_cast<uint2*>(lv);
}

__global__ __launch_bounds__(256) void w7_split_kernel(const float* __restrict__ w7) {
    int t = blockIdx.x * blockDim.x + threadIdx.x;
    const int NQ = DDIM * DDIM / 4;
    if (t >= NQ) return;
    float4 v = reinterpret_cast<const float4*>(w7)[t];
    float s[4] = {v.x, v.y, v.z, v.w};
    __nv_bfloat16 hv[4], lv[4];
#pragma unroll
    for (int q = 0; q < 4; q++) split2(s[q], hv[q], lv[q]);
    size_t idx = (size_t)t * 4;
    *reinterpret_cast<uint2*>(&g_w7h[idx]) = *reinterpret_cast<uint2*>(hv);
    *reinterpret_cast<uint2*>(&g_w7l[idx]) = *reinterpret_cast<uint2*>(lv);
}

// ---------------------------------------------------------------------------
// bf16x3 GEMM via mma.sync (HMMA):
//   C[M,N] = relu(bias + A·B^T), A·B^T ≈ Ah·Bh + Ah·Bl + Al·Bh
// BM=BN=128, BK=64 bf16. 4 warps, warp tile 64x64. 3-stage cp.async pipeline.
// mode 0: fp32 out; mode 1: bf16 hi/lo out.
// ---------------------------------------------------------------------------
#define NST 3
#define STAGE_B 32768            // A 16KB + B 16KB
#define GEMM_SMEM (NST * STAGE_B)

__device__ __forceinline__ void load_stage(
    const __nv_bfloat16* __restrict__ A, const __nv_bfloat16* __restrict__ B,
    int Kb, int bm0, int bn0, int k0, uint32_t sbase, int tid) {
#pragma unroll
    for (int it = 0; it < 16; it++) {
        int f = tid + it * 128;
        int isB = f >> 10;
        int fl = f & 1023;
        int r = fl >> 3, g = fl & 7;
        const __nv_bfloat16* src = isB
            ? (B + (size_t)(bn0 + r) * Kb + k0 + g * 8)
            : (A + (size_t)(bm0 + r) * Kb + k0 + g * 8);
        uint32_t dst = sbase + (isB ? 16384u : 0u) + swz(r, g);
        CP_ASYNC16(dst, src);
    }
}

__global__ __launch_bounds__(128) void gemm_mma(
    const __nv_bfloat16* __restrict__ Ah, const __nv_bfloat16* __restrict__ Al,
    const __nv_bfloat16* __restrict__ Bh, const __nv_bfloat16* __restrict__ Bl,
    const float* __restrict__ bias, int Kb, int mode,
    float* __restrict__ Cf, __nv_bfloat16* __restrict__ Ch, __nv_bfloat16* __restrict__ Cl) {
    extern __shared__ __align__(128) char smp[];
    uint32_t s0 = smem_u32(smp);

    int tid = threadIdx.x;
    int wid = tid >> 5;
    int lane = tid & 31;
    int wm = wid & 1;          // warp row (M)
    int wn = wid >> 1;         // warp col (N)
    int bm0 = blockIdx.y * 128;
    int bn0 = blockIdx.x * 128;

    int lr = lane & 7;
    int a_add8 = (lane >> 3) & 1;   // A: +8 rows for mats 1,3
    int a_gsel = lane >> 4;         // A: k-group for mats 2,3
    int b_add8 = lane >> 4;         // B: +8 rows for mats 2,3
    int b_gsel = (lane >> 3) & 1;   // B: k-group for mats 1,3

    // per-lane row-part offsets (row = base + lr)
    uint32_t aoff[4], boff[4];
#pragma unroll
    for (int mf = 0; mf < 4; mf++)
        aoff[mf] = (uint32_t)(wm * 8 + mf * 2 + a_add8) * 1024u + (uint32_t)lr * 128u;
#pragma unroll
    for (int nf2 = 0; nf2 < 4; nf2++)
        boff[nf2] = (uint32_t)(wn * 8 + nf2 * 2 + b_add8) * 1024u + (uint32_t)lr * 128u;

    float acc[4][8][4];
#pragma unroll
    for (int i = 0; i < 4; i++)
#pragma unroll
        for (int j = 0; j < 8; j++)
#pragma unroll
            for (int q = 0; q < 4; q++) acc[i][j][q] = 0.f;

    int cpt = Kb >> 6;
    int nch = 3 * cpt;

    // chunk -> (A,B,k0) resolver
    auto resolve = [&](int kb, const __nv_bfloat16*& A, const __nv_bfloat16*& B, int& k0) {
        int third = (kb >= 2 * cpt) ? 2 : ((kb >= cpt) ? 1 : 0);
        A = (third == 2) ? Al : Ah;
        B = (third == 1) ? Bl : Bh;
        k0 = (kb - third * cpt) << 6;
    };

    // prologue: stages 0,1
    {
        const __nv_bfloat16 *A, *B; int k0;
        resolve(0, A, B, k0);
        load_stage(A, B, Kb, bm0, bn0, k0, s0, tid);
        CP_COMMIT();
        resolve(1, A, B, k0);
        load_stage(A, B, Kb, bm0, bn0, k0, s0 + STAGE_B, tid);
        CP_COMMIT();
    }

    for (int kb = 0; kb < nch; kb++) {
        CP_WAIT1();
        __syncthreads();

        int nk = kb + 2;
        if (nk < nch) {
            const __nv_bfloat16 *A, *B; int k0;
            resolve(nk, A, B, k0);
            int slot = nk % NST;
            load_stage(A, B, Kb, bm0, bn0, k0, s0 + slot * STAGE_B, tid);
            CP_COMMIT();
        }

        uint32_t abase = s0 + (kb % NST) * STAGE_B;
        uint32_t bbase = abase + 16384u;

#pragma unroll
        for (int ks = 0; ks < 4; ks++) {
            uint32_t a[4][4], b[4][4];
#pragma unroll
            for (int mf = 0; mf < 4; mf++) {
                uint32_t addr = abase + aoff[mf] + (uint32_t)(((2 * ks + a_gsel) ^ lr) << 4);
                LDSM_X4(a[mf][0], a[mf][1], a[mf][2], a[mf][3], addr);
            }
#pragma unroll
            for (int nf2 = 0; nf2 < 4; nf2++) {
                uint32_t addr = bbase + boff[nf2] + (uint32_t)(((2 * ks + b_gsel) ^ lr) << 4);
                LDSM_X4(b[nf2][0], b[nf2][1], b[nf2][2], b[nf2][3], addr);
            }
#pragma unroll
            for (int mf = 0; mf < 4; mf++)
#pragma unroll
                for (int nf = 0; nf < 8; nf++) {
                    uint32_t b0 = b[nf >> 1][(nf & 1) * 2];
                    uint32_t b1 = b[nf >> 1][(nf & 1) * 2 + 1];
                    MMA_BF16(acc[mf][nf], a[mf][0], a[mf][1], a[mf][2], a[mf][3], b0, b1);
                }
        }
    }

    // epilogue
    int gid = lane >> 2, tig = lane & 3;
#pragma unroll
    for (int mf = 0; mf < 4; mf++) {
#pragma unroll
        for (int nf = 0; nf < 8; nf++) {
            int row0 = bm0 + wm * 64 + mf * 16 + gid;
            int col = bn0 + wn * 64 + nf * 8 + tig * 2;
            float bx = __ldg(&bias[col]);
            float by = __ldg(&bias[col + 1]);
            float v00 = fmaxf(acc[mf][nf][0] + bx, 0.f);
            float v01 = fmaxf(acc[mf][nf][1] + by, 0.f);
            float v10 = fmaxf(acc[mf][nf][2] + bx, 0.f);
            float v11 = fmaxf(acc[mf][nf][3] + by, 0.f);
            if (mode == 0) {
                *reinterpret_cast<float2*>(&Cf[(size_t)row0 * DDIM + col]) = make_float2(v00, v01);
                *reinterpret_cast<float2*>(&Cf[(size_t)(row0 + 8) * DDIM + col]) = make_float2(v10, v11);
            } else {
                __nv_bfloat16 h0, l0, h1, l1;
                split2(v00, h0, l0); split2(v01, h1, l1);
                __nv_bfloat162 hp, lp;
                hp.x = h0; hp.y = h1; lp.x = l0; lp.y = l1;
                *reinterpret_cast<__nv_bfloat162*>(&Ch[(size_t)row0 * DDIM + col]) = hp;
                *reinterpret_cast<__nv_bfloat162*>(&Cl[(size_t)row0 * DDIM + col]) = lp;
                split2(v10, h0, l0); split2(v11, h1, l1);
                hp.x = h0; hp.y = h1; lp.x = l0; lp.y = l1;
                *reinterpret_cast<__nv_bfloat162*>(&Ch[(size_t)(row0 + 8) * DDIM + col]) = hp;
                *reinterpret_cast<__nv_bfloat162*>(&Cl[(size_t)(row0 + 8) * DDIM + col]) = lp;
            }
        }
    }
}

// ---------------------------------------------------------------------------
// Heads split-K GEMM: partial[ks][r][c] over K slices of 512
// ---------------------------------------------------------------------------
__global__ __launch_bounds__(256) void heads_partial(const float* __restrict__ w8c,
                                                     const float* __restrict__ w8d) {
    __shared__ float As[32][132];
    __shared__ float Bs[32][48];
    int r0 = blockIdx.x * 128;
    int ks = blockIdx.y;
    int k0 = ks * 512;
    int t = threadIdx.x;
    int ty = t >> 3, tx = t & 7;

    float acc[4][6];
#pragma unroll
    for (int i = 0; i < 4; i++)
#pragma unroll
        for (int j = 0; j < 6; j++) acc[i][j] = 0.f;

    for (int kc = 0; kc < 512; kc += 32) {
        for (int f = t; f < 1024; f += 256) {
            int r = f >> 3, q = f & 7;
            float4 v = *reinterpret_cast<const float4*>(&g_h2[(size_t)(r0 + r) * DDIM + k0 + kc + q * 4]);
            As[q * 4 + 0][r] = v.x; As[q * 4 + 1][r] = v.y;
            As[q * 4 + 2][r] = v.z; As[q * 4 + 3][r] = v.w;
        }
        for (int f = t; f < 336; f += 256) {
            int c = f >> 3, q = f & 7;
            const float* wr = (c < 21) ? (w8c + (size_t)c * DDIM) : (w8d + (size_t)(c - 21) * DDIM);
            float4 v = *reinterpret_cast<const float4*>(wr + k0 + kc + q * 4);
            Bs[q * 4 + 0][c] = v.x; Bs[q * 4 + 1][c] = v.y;
            Bs[q * 4 + 2][c] = v.z; Bs[q * 4 + 3][c] = v.w;
        }
        __syncthreads();
#pragma unroll
        for (int kk = 0; kk < 32; kk++) {
            float a[4], b[6];
#pragma unroll
            for (int i = 0; i < 4; i++) a[i] = As[kk][ty * 4 + i];
#pragma unroll
            for (int j = 0; j < 6; j++) b[j] = Bs[kk][tx * 6 + j];
#pragma unroll
            for (int i = 0; i < 4; i++)
#pragma unroll
                for (int j = 0; j < 6; j++) acc[i][j] = fmaf(a[i], b[j], acc[i][j]);
        }
        __syncthreads();
    }
#pragma unroll
    for (int i = 0; i < 4; i++) {
        int r = r0 + ty * 4 + i;
#pragma unroll
        for (int j = 0; j < 6; j++) {
            g_hpart[(size_t)ks * R_ROIS * 48 + (size_t)r * 48 + tx * 6 + j] = acc[i][j];
        }
    }
}

__global__ __launch_bounds__(256) void heads_reduce(const float* __restrict__ b8c,
                                                    const float* __restrict__ b8d) {
    int i = blockIdx.x * 256 + threadIdx.x;
    if (i >= R_ROIS * 42) return;
    int r = i / 42, c = i - r * 42;
    float s = 0.f;
#pragma unroll
    for (int ks = 0; ks < 8; ks++) s += g_hpart[(size_t)ks * R_ROIS * 48 + (size_t)r * 48 + c];
    if (c < 21) g_xc[r * NCLS + c] = fmaxf(s + b8c[c], 0.f);
    else        g_xd[r * NCLS + (c - 21)] = fmaxf(s + b8d[c - 21], 0.f);
}

// ---------------------------------------------------------------------------
// Softmax epilogue
// ---------------------------------------------------------------------------
__global__ __launch_bounds__(256) void colstats_kernel() {
    __shared__ float red[256];
    int c = blockIdx.x;
    int t = threadIdx.x;
    float m = -INFINITY;
    for (int r = t; r < R_ROIS; r += 256) m = fmaxf(m, g_xd[r * NCLS + c]);
    red[t] = m;
    __syncthreads();
    for (int s = 128; s; s >>= 1) {
        if (t < s) red[t] = fmaxf(red[t], red[t + s]);
        __syncthreads();
    }
    float cm = red[0];
    __syncthreads();
    float s2 = 0.f;
    for (int r = t; r < R_ROIS; r += 256) s2 += expf(g_xd[r * NCLS + c] - cm);
    red[t] = s2;
    __syncthreads();
    for (int s = 128; s; s >>= 1) {
        if (t < s) red[t] += red[t + s];
        __syncthreads();
    }
    if (t == 0) { g_colmax[c] = cm; g_colsum[c] = red[0]; }
}

__global__ __launch_bounds__(256) void finalize_kernel(float* __restrict__ out) {
    int warp = threadIdx.x >> 5;
    int lane = threadIdx.x & 31;
    int r = blockIdx.x * 8 + warp;
    if (r >= R_ROIS) return;

    float v = (lane < NCLS) ? g_xc[r * NCLS + lane] : -INFINITY;
    float m = v;
#pragma unroll
    for (int off = 16; off; off >>= 1) m = fmaxf(m, __shfl_xor_sync(0xFFFFFFFFu, m, off));
    float e = (lane < NCLS) ? expf(v - m) : 0.f;
    float s = e;
#pragma unroll
    for (int off = 16; off; off >>= 1) s += __shfl_xor_sync(0xFFFFFFFFu, s, off);

    if (lane < NCLS) {
        float dr = e / s;
        float smd = expf(g_xd[r * NCLS + lane] - g_colmax[lane]) / g_colsum[lane];
        out[OUT_DM + r * NCLS + lane] = dr * smd;
        out[OUT_DR + r * NCLS + lane] = dr;
    }
}

__global__ __launch_bounds__(256) void score_kernel(const float* __restrict__ dm,
                                                    float* __restrict__ score) {
    __shared__ float red[256];
    int c = blockIdx.x;
    int t = threadIdx.x;
    float s = 0.f;
    for (int r = t; r < R_ROIS; r += 256) s += dm[r * NCLS + c];
    red[t] = s;
    __syncthreads();
    for (int st = 128; st; st >>= 1) {
        if (t < st) red[t] += red[t + st];
        __syncthreads();
    }
    if (t == 0) score[c] = red[0];
}

// ---------------------------------------------------------------------------
// Launch
// ---------------------------------------------------------------------------
extern "C" void kernel_launch(void* const* d_in, const int* in_sizes, int n_in,
                              void* d_out, int out_size) {
    const float* x   = (const float*)d_in[0];
    const float* w6  = (const float*)d_in[1];
    const float* b6  = (const float*)d_in[2];
    const float* w7  = (const float*)d_in[3];
    const float* b7  = (const float*)d_in[4];
    const float* w8c = (const float*)d_in[5];
    const float* b8c = (const float*)d_in[6];
    const float* w8d = (const float*)d_in[7];
    const float* b8d = (const float*)d_in[8];
    const int*   ssw = (const int*)d_in[9];
    float* out = (float*)d_out;

    __nv_bfloat16 *p_yh, *p_yl, *p_w6h, *p_w6l, *p_w7h, *p_w7l, *p_h1h, *p_h1l;
    float *p_h2;
    cudaGetSymbolAddress((void**)&p_yh, g_yh);
    cudaGetSymbolAddress((void**)&p_yl, g_yl);
    cudaGetSymbolAddress((void**)&p_w6h, g_w6h);
    cudaGetSymbolAddress((void**)&p_w6l, g_w6l);
    cudaGetSymbolAddress((void**)&p_w7h, g_w7h);
    cudaGetSymbolAddress((void**)&p_w7l, g_w7l);
    cudaGetSymbolAddress((void**)&p_h1h, g_h1h);
    cudaGetSymbolAddress((void**)&p_h1l, g_h1l);
    cudaGetSymbolAddress((void**)&p_h2, g_h2);

    cudaFuncSetAttribute(gemm_mma, cudaFuncAttributeMaxDynamicSharedMemorySize, GEMM_SMEM);

    // 1) SPP -> y hi/lo
    spp_kernel<<<R_ROIS, 256>>>(x, ssw);

    // 2) fold + split weights
    wsum_split_kernel<<<(DDIM * KHALF / 4 + 255) / 256, 256>>>(w6);
    w7_split_kernel<<<(DDIM * DDIM / 4 + 255) / 256, 256>>>(w7);

    // 3) FC6 (bf16x3 mma.sync): h1 = relu(y·wsum6^T + b6) -> bf16 hi/lo
    {
        dim3 grid(DDIM / 128, R_ROIS / 128);
        gemm_mma<<<grid, 128, GEMM_SMEM>>>(p_yh, p_yl, p_w6h, p_w6l, b6, KHALF, 1,
                                           nullptr, p_h1h, p_h1l);
    }

    // 4) FC7: h2 = relu(h1·w7^T + b7) -> fp32
    {
        dim3 grid(DDIM / 128, R_ROIS / 128);
        gemm_mma<<<grid, 128, GEMM_SMEM>>>(p_h1h, p_h1l, p_w7h, p_w7l, b7, DDIM, 0,
                                           p_h2, nullptr, nullptr);
    }

    // 5) heads
    {
        dim3 grid(R_ROIS / 128, 8);
        heads_partial<<<grid, 256>>>(w8c, w8d);
        heads_reduce<<<(R_ROIS * 42 + 255) / 256, 256>>>(b8c, b8d);
    }

    // 6) softmax stats + finalize + score
    colstats_kernel<<<NCLS, 256>>>();
    finalize_kernel<<<R_ROIS / 8, 256>>>(out);
    score_kernel<<<NCLS, 256>>>(out + OUT_DM, out + OUT_SC);
}

// round 4
// speedup vs baseline: 2.7402x; 1.1025x over previous
#include <cuda_runtime.h>
#include <cuda_bf16.h>
#include <math.h>
#include <stdint.h>

// ---------------------------------------------------------------------------
// Problem constants
// ---------------------------------------------------------------------------
#define R_ROIS 2048
#define CCH    512
#define HWDIM  64
#define DDIM   4096
#define NCLS   21
#define KHALF  2048
#define NORI   58            // valid 7x7-window origins per axis (0..57)

#define OUT_DM 0
#define OUT_DR (R_ROIS * NCLS)
#define OUT_SC (2 * R_ROIS * NCLS)

// ---------------------------------------------------------------------------
// Scratch (device globals)
// ---------------------------------------------------------------------------
__device__ float g_hmax[CCH * HWDIM * HWDIM];        // horizontal 7-max, [c][y][x']
__device__ float g_vmax[NORI * NORI * CCH];          // full 7x7 max, [y'][x'][c]
__device__ __nv_bfloat16 g_yh[R_ROIS * KHALF];
__device__ __nv_bfloat16 g_yl[R_ROIS * KHALF];
__device__ __nv_bfloat16 g_w6h[DDIM * KHALF];
__device__ __nv_bfloat16 g_w6l[DDIM * KHALF];
__device__ __nv_bfloat16 g_w7h[DDIM * DDIM];
__device__ __nv_bfloat16 g_w7l[DDIM * DDIM];
__device__ __nv_bfloat16 g_h1h[R_ROIS * DDIM];
__device__ __nv_bfloat16 g_h1l[R_ROIS * DDIM];
__device__ float g_h2[R_ROIS * DDIM];
__device__ float g_hpart[8 * R_ROIS * 48];
__device__ float g_xc[R_ROIS * NCLS];
__device__ float g_xd[R_ROIS * NCLS];
__device__ float g_colmax[NCLS];
__device__ float g_colsum[NCLS];

// ---------------------------------------------------------------------------
// Helpers
// ---------------------------------------------------------------------------
__device__ __forceinline__ uint32_t smem_u32(const void* p) {
    uint32_t a;
    asm("{ .reg .u64 t; cvta.to.shared.u64 t, %1; cvt.u32.u64 %0, t; }" : "=r"(a) : "l"(p));
    return a;
}

__device__ __forceinline__ void split2(float v, __nv_bfloat16& h, __nv_bfloat16& l) {
    h = __float2bfloat16_rn(v);
    l = __float2bfloat16_rn(v - __bfloat162float(h));
}

// swizzled byte offset inside a [rows x 64 bf16] (128 B/row) SW128 tile
__device__ __forceinline__ uint32_t swz(int r, int g) {
    return (uint32_t)(r >> 3) * 1024u + (uint32_t)(r & 7) * 128u
         + (uint32_t)((g ^ (r & 7)) << 4);
}

#define CP_ASYNC16(dst, src) \
    asm volatile("cp.async.cg.shared.global [%0], [%1], 16;" :: "r"(dst), "l"(src))
#define CP_COMMIT() asm volatile("cp.async.commit_group;" ::: "memory")
#define CP_WAIT1()  asm volatile("cp.async.wait_group 1;" ::: "memory")

#define LDSM_X4(r0, r1, r2, r3, addr) \
    asm volatile("ldmatrix.sync.aligned.m8n8.x4.shared.b16 {%0,%1,%2,%3}, [%4];" \
                 : "=r"(r0), "=r"(r1), "=r"(r2), "=r"(r3) : "r"(addr))

#define MMA_BF16(c, a0, a1, a2, a3, b0, b1) \
    asm volatile("mma.sync.aligned.m16n8k16.row.col.f32.bf16.bf16.f32 " \
                 "{%0,%1,%2,%3}, {%4,%5,%6,%7}, {%8,%9}, {%0,%1,%2,%3};" \
                 : "+f"((c)[0]), "+f"((c)[1]), "+f"((c)[2]), "+f"((c)[3]) \
                 : "r"(a0), "r"(a1), "r"(a2), "r"(a3), "r"(b0), "r"(b1))

// ---------------------------------------------------------------------------
// SPP pass 1: horizontal 7-max.  g_hmax[c][y][x'] = max_{d<7} x[c][y][x'+d]
// ---------------------------------------------------------------------------
__global__ __launch_bounds__(256) void hmax_kernel(const float* __restrict__ x) {
    int row = blockIdx.x * 4 + (threadIdx.x >> 6);      // c*64 + y
    int xp = threadIdx.x & 63;
    if (xp >= NORI) return;
    const float* src = x + (size_t)row * HWDIM + xp;
    float m = src[0];
#pragma unroll
    for (int d = 1; d < 7; d++) m = fmaxf(m, src[d]);
    g_hmax[(size_t)row * HWDIM + xp] = m;
}

// ---------------------------------------------------------------------------
// SPP pass 2: vertical 7-max + transpose to [y'][x'][c].
// block = (y', cgrp of 4), threads (64 x-lanes, 4 c)
// ---------------------------------------------------------------------------
__global__ __launch_bounds__(256) void vmax_kernel() {
    int yp = blockIdx.x;
    int c = blockIdx.y * 4 + threadIdx.y;
    int xp = threadIdx.x;
    if (xp >= NORI) return;
    const float* src = g_hmax + (size_t)c * HWDIM * HWDIM + (size_t)yp * HWDIM + xp;
    float m = src[0];
#pragma unroll
    for (int d = 1; d < 7; d++) m = fmaxf(m, src[d * HWDIM]);
    g_vmax[((size_t)yp * NORI + xp) * CCH + c] = m;
}

// ---------------------------------------------------------------------------
// SPP gather: per ROI, y[r, c*4 + (i*2+j)] = M[y0+7i][x0+7j][c], bf16 hi/lo
// ---------------------------------------------------------------------------
__global__ __launch_bounds__(256) void spp_gather_kernel(const int* __restrict__ ssw) {
    __shared__ float ys[KHALF];
    int r = blockIdx.x;
    int y0 = ssw[r * 4 + 0];
    int x0 = ssw[r * 4 + 1];
    int t = threadIdx.x;
#pragma unroll
    for (int q = 0; q < 4; q++) {
        int i = q >> 1, j = q & 1;
        const float* src = g_vmax + ((size_t)(y0 + 7 * i) * NORI + (x0 + 7 * j)) * CCH;
        for (int c0 = 0; c0 < CCH; c0 += 256) {
            int c = c0 + t;
            ys[c * 4 + q] = src[c];
        }
    }
    __syncthreads();
    // each thread writes 8 consecutive outputs (one uint4 of hi, one of lo)
    int k0 = t * 8;
    __nv_bfloat16 hv[8], lv[8];
#pragma unroll
    for (int u = 0; u < 8; u++) split2(ys[k0 + u], hv[u], lv[u]);
    *reinterpret_cast<uint4*>(&g_yh[(size_t)r * KHALF + k0]) = *reinterpret_cast<uint4*>(hv);
    *reinterpret_cast<uint4*>(&g_yl[(size_t)r * KHALF + k0]) = *reinterpret_cast<uint4*>(lv);
}

// ---------------------------------------------------------------------------
// Weight fold + split
// ---------------------------------------------------------------------------
__global__ __launch_bounds__(256) void wsum_split_kernel(const float* __restrict__ w6) {
    int t = blockIdx.x * blockDim.x + threadIdx.x;
    const int NQ = DDIM * KHALF / 4;
    if (t >= NQ) return;
    int e = t / (KHALF / 4);
    int kq = t - e * (KHALF / 4);
    float4 av = reinterpret_cast<const float4*>(w6 + (size_t)e * DDIM)[kq];
    float4 bv = reinterpret_cast<const float4*>(w6 + (size_t)e * DDIM + KHALF)[kq];
    float s[4] = {av.x + bv.x, av.y + bv.y, av.z + bv.z, av.w + bv.w};
    __nv_bfloat16 hv[4], lv[4];
#pragma unroll
    for (int q = 0; q < 4; q++) split2(s[q], hv[q], lv[q]);
    size_t idx = (size_t)e * KHALF + kq * 4;
    *reinterpret_cast<uint2*>(&g_w6h[idx]) = *reinterpret_cast<uint2*>(hv);
    *reinterpret_cast<uint2*>(&g_w6l[idx]) = *reinterpret_cast<uint2*>(lv);
}

__global__ __launch_bounds__(256) void w7_split_kernel(const float* __restrict__ w7) {
    int t = blockIdx.x * blockDim.x + threadIdx.x;
    const int NQ = DDIM * DDIM / 4;
    if (t >= NQ) return;
    float4 v = reinterpret_cast<const float4*>(w7)[t];
    float s[4] = {v.x, v.y, v.z, v.w};
    __nv_bfloat16 hv[4], lv[4];
#pragma unroll
    for (int q = 0; q < 4; q++) split2(s[q], hv[q], lv[q]);
    size_t idx = (size_t)t * 4;
    *reinterpret_cast<uint2*>(&g_w7h[idx]) = *reinterpret_cast<uint2*>(hv);
    *reinterpret_cast<uint2*>(&g_w7l[idx]) = *reinterpret_cast<uint2*>(lv);
}

// ---------------------------------------------------------------------------
// bf16x3 GEMM via mma.sync: C = relu(bias + A·B^T), A·B^T ≈ AhBh + AhBl + AlBh
// CTA tile 256(M) x 128(N), BK=64. 512 threads = 16 warps, warp tile 64x32.
// 3-stage cp.async pipeline. mode 0: fp32 out; mode 1: bf16 hi/lo out.
// ---------------------------------------------------------------------------
#define NST 3
#define STAGE_B 49152            // A 32KB + B 16KB
#define GEMM_SMEM (NST * STAGE_B)

__device__ __forceinline__ void load_stage(
    const __nv_bfloat16* __restrict__ A, const __nv_bfloat16* __restrict__ B,
    int Kb, int bm0, int bn0, int k0, uint32_t sbase, int tid) {
#pragma unroll
    for (int it = 0; it < 6; it++) {
        int f = tid + it * 512;            // 0..3071 uint4 slots
        int isB = (f >= 2048);
        int fl = isB ? (f - 2048) : f;
        int r = fl >> 3, g = fl & 7;
        const __nv_bfloat16* src = isB
            ? (B + (size_t)(bn0 + r) * Kb + k0 + g * 8)
            : (A + (size_t)(bm0 + r) * Kb + k0 + g * 8);
        uint32_t dst = sbase + (isB ? 32768u : 0u) + swz(r, g);
        CP_ASYNC16(dst, src);
    }
}

__global__ __launch_bounds__(512, 1) void gemm_mma(
    const __nv_bfloat16* __restrict__ Ah, const __nv_bfloat16* __restrict__ Al,
    const __nv_bfloat16* __restrict__ Bh, const __nv_bfloat16* __restrict__ Bl,
    const float* __restrict__ bias, int Kb, int mode,
    float* __restrict__ Cf, __nv_bfloat16* __restrict__ Ch, __nv_bfloat16* __restrict__ Cl) {
    extern __shared__ __align__(128) char smp[];
    uint32_t s0 = smem_u32(smp);

    int tid = threadIdx.x;
    int wid = tid >> 5;
    int lane = tid & 31;
    int wm = wid & 3;          // warp row: 64 M-rows each
    int wn = wid >> 2;         // warp col: 32 N-cols each
    int bm0 = blockIdx.y * 256;
    int bn0 = blockIdx.x * 128;

    int lr = lane & 7;
    int a_add8 = (lane >> 3) & 1;
    int a_gsel = lane >> 4;
    int b_add8 = lane >> 4;
    int b_gsel = (lane >> 3) & 1;

    uint32_t aoff[4], boff[2];
#pragma unroll
    for (int mf = 0; mf < 4; mf++)
        aoff[mf] = (uint32_t)(wm * 8 + mf * 2 + a_add8) * 1024u + (uint32_t)lr * 128u;
#pragma unroll
    for (int nf2 = 0; nf2 < 2; nf2++)
        boff[nf2] = (uint32_t)(wn * 4 + nf2 * 2 + b_add8) * 1024u + (uint32_t)lr * 128u;

    float acc[4][4][4];
#pragma unroll
    for (int i = 0; i < 4; i++)
#pragma unroll
        for (int j = 0; j < 4; j++)
#pragma unroll
            for (int q = 0; q < 4; q++) acc[i][j][q] = 0.f;

    int cpt = Kb >> 6;
    int nch = 3 * cpt;

    auto resolve = [&](int kb, const __nv_bfloat16*& A, const __nv_bfloat16*& B, int& k0) {
        int third = (kb >= 2 * cpt) ? 2 : ((kb >= cpt) ? 1 : 0);
        A = (third == 2) ? Al : Ah;
        B = (third == 1) ? Bl : Bh;
        k0 = (kb - third * cpt) << 6;
    };

    {
        const __nv_bfloat16 *A, *B; int k0;
        resolve(0, A, B, k0);
        load_stage(A, B, Kb, bm0, bn0, k0, s0, tid);
        CP_COMMIT();
        resolve(1, A, B, k0);
        load_stage(A, B, Kb, bm0, bn0, k0, s0 + STAGE_B, tid);
        CP_COMMIT();
    }

    for (int kb = 0; kb < nch; kb++) {
        CP_WAIT1();
        __syncthreads();

        int nk = kb + 2;
        if (nk < nch) {
            const __nv_bfloat16 *A, *B; int k0;
            resolve(nk, A, B, k0);
            load_stage(A, B, Kb, bm0, bn0, k0, s0 + (nk % NST) * STAGE_B, tid);
            CP_COMMIT();
        }

        uint32_t abase = s0 + (kb % NST) * STAGE_B;
        uint32_t bbase = abase + 32768u;

#pragma unroll
        for (int ks = 0; ks < 4; ks++) {
            uint32_t a[4][4], b[2][4];
#pragma unroll
            for (int mf = 0; mf < 4; mf++) {
                uint32_t addr = abase + aoff[mf] + (uint32_t)(((2 * ks + a_gsel) ^ lr) << 4);
                LDSM_X4(a[mf][0], a[mf][1], a[mf][2], a[mf][3], addr);
            }
#pragma unroll
            for (int nf2 = 0; nf2 < 2; nf2++) {
                uint32_t addr = bbase + boff[nf2] + (uint32_t)(((2 * ks + b_gsel) ^ lr) << 4);
                LDSM_X4(b[nf2][0], b[nf2][1], b[nf2][2], b[nf2][3], addr);
            }
#pragma unroll
            for (int mf = 0; mf < 4; mf++)
#pragma unroll
                for (int nf = 0; nf < 4; nf++) {
                    uint32_t b0 = b[nf >> 1][(nf & 1) * 2];
                    uint32_t b1 = b[nf >> 1][(nf & 1) * 2 + 1];
                    MMA_BF16(acc[mf][nf], a[mf][0], a[mf][1], a[mf][2], a[mf][3], b0, b1);
                }
        }
    }

    int gid = lane >> 2, tig = lane & 3;
#pragma unroll
    for (int mf = 0; mf < 4; mf++) {
#pragma unroll
        for (int nf = 0; nf < 4; nf++) {
            int row0 = bm0 + wm * 64 + mf * 16 + gid;
            int col = bn0 + wn * 32 + nf * 8 + tig * 2;
            float bx = __ldg(&bias[col]);
            float by = __ldg(&bias[col + 1]);
            float v00 = fmaxf(acc[mf][nf][0] + bx, 0.f);
            float v01 = fmaxf(acc[mf][nf][1] + by, 0.f);
            float v10 = fmaxf(acc[mf][nf][2] + bx, 0.f);
            float v11 = fmaxf(acc[mf][nf][3] + by, 0.f);
            if (mode == 0) {
                *reinterpret_cast<float2*>(&Cf[(size_t)row0 * DDIM + col]) = make_float2(v00, v01);
                *reinterpret_cast<float2*>(&Cf[(size_t)(row0 + 8) * DDIM + col]) = make_float2(v10, v11);
            } else {
                __nv_bfloat16 h0, l0, h1, l1;
                split2(v00, h0, l0); split2(v01, h1, l1);
                __nv_bfloat162 hp, lp;
                hp.x = h0; hp.y = h1; lp.x = l0; lp.y = l1;
                *reinterpret_cast<__nv_bfloat162*>(&Ch[(size_t)row0 * DDIM + col]) = hp;
                *reinterpret_cast<__nv_bfloat162*>(&Cl[(size_t)row0 * DDIM + col]) = lp;
                split2(v10, h0, l0); split2(v11, h1, l1);
                hp.x = h0; hp.y = h1; lp.x = l0; lp.y = l1;
                *reinterpret_cast<__nv_bfloat162*>(&Ch[(size_t)(row0 + 8) * DDIM + col]) = hp;
                *reinterpret_cast<__nv_bfloat162*>(&Cl[(size_t)(row0 + 8) * DDIM + col]) = lp;
            }
        }
    }
}

// ---------------------------------------------------------------------------
// Heads split-K GEMM
// ---------------------------------------------------------------------------
__global__ __launch_bounds__(256) void heads_partial(const float* __restrict__ w8c,
                                                     const float* __restrict__ w8d) {
    __shared__ float As[32][132];
    __shared__ float Bs[32][48];
    int r0 = blockIdx.x * 128;
    int ks = blockIdx.y;
    int k0 = ks * 512;
    int t = threadIdx.x;
    int ty = t >> 3, tx = t & 7;

    float acc[4][6];
#pragma unroll
    for (int i = 0; i < 4; i++)
#pragma unroll
        for (int j = 0; j < 6; j++) acc[i][j] = 0.f;

    for (int kc = 0; kc < 512; kc += 32) {
        for (int f = t; f < 1024; f += 256) {
            int r = f >> 3, q = f & 7;
            float4 v = *reinterpret_cast<const float4*>(&g_h2[(size_t)(r0 + r) * DDIM + k0 + kc + q * 4]);
            As[q * 4 + 0][r] = v.x; As[q * 4 + 1][r] = v.y;
            As[q * 4 + 2][r] = v.z; As[q * 4 + 3][r] = v.w;
        }
        for (int f = t; f < 336; f += 256) {
            int c = f >> 3, q = f & 7;
            const float* wr = (c < 21) ? (w8c + (size_t)c * DDIM) : (w8d + (size_t)(c - 21) * DDIM);
            float4 v = *reinterpret_cast<const float4*>(wr + k0 + kc + q * 4);
            Bs[q * 4 + 0][c] = v.x; Bs[q * 4 + 1][c] = v.y;
            Bs[q * 4 + 2][c] = v.z; Bs[q * 4 + 3][c] = v.w;
        }
        __syncthreads();
#pragma unroll
        for (int kk = 0; kk < 32; kk++) {
            float a[4], b[6];
#pragma unroll
            for (int i = 0; i < 4; i++) a[i] = As[kk][ty * 4 + i];
#pragma unroll
            for (int j = 0; j < 6; j++) b[j] = Bs[kk][tx * 6 + j];
#pragma unroll
            for (int i = 0; i < 4; i++)
#pragma unroll
                for (int j = 0; j < 6; j++) acc[i][j] = fmaf(a[i], b[j], acc[i][j]);
        }
        __syncthreads();
    }
#pragma unroll
    for (int i = 0; i < 4; i++) {
        int r = r0 + ty * 4 + i;
#pragma unroll
        for (int j = 0; j < 6; j++) {
            g_hpart[(size_t)ks * R_ROIS * 48 + (size_t)r * 48 + tx * 6 + j] = acc[i][j];
        }
    }
}

__global__ __launch_bounds__(256) void heads_reduce(const float* __restrict__ b8c,
                                                    const float* __restrict__ b8d) {
    int i = blockIdx.x * 256 + threadIdx.x;
    if (i >= R_ROIS * 42) return;
    int r = i / 42, c = i - r * 42;
    float s = 0.f;
#pragma unroll
    for (int ks = 0; ks < 8; ks++) s += g_hpart[(size_t)ks * R_ROIS * 48 + (size_t)r * 48 + c];
    if (c < 21) g_xc[r * NCLS + c] = fmaxf(s + b8c[c], 0.f);
    else        g_xd[r * NCLS + (c - 21)] = fmaxf(s + b8d[c - 21], 0.f);
}

// ---------------------------------------------------------------------------
// Softmax epilogue
// ---------------------------------------------------------------------------
__global__ __launch_bounds__(256) void colstats_kernel() {
    __shared__ float red[256];
    int c = blockIdx.x;
    int t = threadIdx.x;
    float m = -INFINITY;
    for (int r = t; r < R_ROIS; r += 256) m = fmaxf(m, g_xd[r * NCLS + c]);
    red[t] = m;
    __syncthreads();
    for (int s = 128; s; s >>= 1) {
        if (t < s) red[t] = fmaxf(red[t], red[t + s]);
        __syncthreads();
    }
    float cm = red[0];
    __syncthreads();
    float s2 = 0.f;
    for (int r = t; r < R_ROIS; r += 256) s2 += expf(g_xd[r * NCLS + c] - cm);
    red[t] = s2;
    __syncthreads();
    for (int s = 128; s; s >>= 1) {
        if (t < s) red[t] += red[t + s];
        __syncthreads();
    }
    if (t == 0) { g_colmax[c] = cm; g_colsum[c] = red[0]; }
}

__global__ __launch_bounds__(256) void finalize_kernel(float* __restrict__ out) {
    int warp = threadIdx.x >> 5;
    int lane = threadIdx.x & 31;
    int r = blockIdx.x * 8 + warp;
    if (r >= R_ROIS) return;

    float v = (lane < NCLS) ? g_xc[r * NCLS + lane] : -INFINITY;
    float m = v;
#pragma unroll
    for (int off = 16; off; off >>= 1) m = fmaxf(m, __shfl_xor_sync(0xFFFFFFFFu, m, off));
    float e = (lane < NCLS) ? expf(v - m) : 0.f;
    float s = e;
#pragma unroll
    for (int off = 16; off; off >>= 1) s += __shfl_xor_sync(0xFFFFFFFFu, s, off);

    if (lane < NCLS) {
        float dr = e / s;
        float smd = expf(g_xd[r * NCLS + lane] - g_colmax[lane]) / g_colsum[lane];
        out[OUT_DM + r * NCLS + lane] = dr * smd;
        out[OUT_DR + r * NCLS + lane] = dr;
    }
}

__global__ __launch_bounds__(256) void score_kernel(const float* __restrict__ dm,
                                                    float* __restrict__ score) {
    __shared__ float red[256];
    int c = blockIdx.x;
    int t = threadIdx.x;
    float s = 0.f;
    for (int r = t; r < R_ROIS; r += 256) s += dm[r * NCLS + c];
    red[t] = s;
    __syncthreads();
    for (int st = 128; st; st >>= 1) {
        if (t < st) red[t] += red[t + st];
        __syncthreads();
    }
    if (t == 0) score[c] = red[0];
}

// ---------------------------------------------------------------------------
// Launch
// ---------------------------------------------------------------------------
extern "C" void kernel_launch(void* const* d_in, const int* in_sizes, int n_in,
                              void* d_out, int out_size) {
    const float* x   = (const float*)d_in[0];
    const float* w6  = (const float*)d_in[1];
    const float* b6  = (const float*)d_in[2];
    const float* w7  = (const float*)d_in[3];
    const float* b7  = (const float*)d_in[4];
    const float* w8c = (const float*)d_in[5];
    const float* b8c = (const float*)d_in[6];
    const float* w8d = (const float*)d_in[7];
    const float* b8d = (const float*)d_in[8];
    const int*   ssw = (const int*)d_in[9];
    float* out = (float*)d_out;

    __nv_bfloat16 *p_yh, *p_yl, *p_w6h, *p_w6l, *p_w7h, *p_w7l, *p_h1h, *p_h1l;
    float *p_h2;
    cudaGetSymbolAddress((void**)&p_yh, g_yh);
    cudaGetSymbolAddress((void**)&p_yl, g_yl);
    cudaGetSymbolAddress((void**)&p_w6h, g_w6h);
    cudaGetSymbolAddress((void**)&p_w6l, g_w6l);
    cudaGetSymbolAddress((void**)&p_w7h, g_w7h);
    cudaGetSymbolAddress((void**)&p_w7l, g_w7l);
    cudaGetSymbolAddress((void**)&p_h1h, g_h1h);
    cudaGetSymbolAddress((void**)&p_h1l, g_h1l);
    cudaGetSymbolAddress((void**)&p_h2, g_h2);

    cudaFuncSetAttribute(gemm_mma, cudaFuncAttributeMaxDynamicSharedMemorySize, GEMM_SMEM);

    // 1) SPP: sliding 7x7 max + per-ROI gather
    hmax_kernel<<<CCH * HWDIM / 4, 256>>>(x);
    {
        dim3 grid(NORI, CCH / 4);
        dim3 blk(64, 4);
        vmax_kernel<<<grid, blk>>>();
    }
    spp_gather_kernel<<<R_ROIS, 256>>>(ssw);

    // 2) fold + split weights
    wsum_split_kernel<<<(DDIM * KHALF / 4 + 255) / 256, 256>>>(w6);
    w7_split_kernel<<<(DDIM * DDIM / 4 + 255) / 256, 256>>>(w7);

    // 3) FC6 (bf16x3): h1 = relu(y·wsum6^T + b6) -> bf16 hi/lo
    {
        dim3 grid(DDIM / 128, R_ROIS / 256);
        gemm_mma<<<grid, 512, GEMM_SMEM>>>(p_yh, p_yl, p_w6h, p_w6l, b6, KHALF, 1,
                                           nullptr, p_h1h, p_h1l);
    }

    // 4) FC7: h2 = relu(h1·w7^T + b7) -> fp32
    {
        dim3 grid(DDIM / 128, R_ROIS / 256);
        gemm_mma<<<grid, 512, GEMM_SMEM>>>(p_h1h, p_h1l, p_w7h, p_w7l, b7, DDIM, 0,
                                           p_h2, nullptr, nullptr);
    }

    // 5) heads
    {
        dim3 grid(R_ROIS / 128, 8);
        heads_partial<<<grid, 256>>>(w8c, w8d);
        heads_reduce<<<(R_ROIS * 42 + 255) / 256, 256>>>(b8c, b8d);
    }

    // 6) softmax stats + finalize + score
    colstats_kernel<<<NCLS, 256>>>();
    finalize_kernel<<<R_ROIS / 8, 256>>>(out);
    score_kernel<<<NCLS, 256>>>(out + OUT_DM, out + OUT_SC);
}

// round 5
// speedup vs baseline: 4.1282x; 1.5065x over previous
#include <cuda_runtime.h>
#include <cuda_fp16.h>
#include <math.h>
#include <stdint.h>

// ---------------------------------------------------------------------------
// Problem constants
// ---------------------------------------------------------------------------
#define R_ROIS 2048
#define CCH    512
#define HWDIM  64
#define DDIM   4096
#define NCLS   21
#define KHALF  2048
#define NORI   58            // valid 7x7-window origins per axis (0..57)

#define OUT_DM 0
#define OUT_DR (R_ROIS * NCLS)
#define OUT_SC (2 * R_ROIS * NCLS)

// ---------------------------------------------------------------------------
// Scratch (device globals)
// ---------------------------------------------------------------------------
__device__ float g_hmax[CCH * HWDIM * HWDIM];        // horizontal 7-max
__device__ float g_vmax[NORI * NORI * CCH];          // 7x7 max, [y'][x'][c]
__device__ __half g_yh[R_ROIS * KHALF];
__device__ __half g_yl[R_ROIS * KHALF];
__device__ __half g_w6h[DDIM * KHALF];
__device__ __half g_w7h[DDIM * DDIM];
__device__ __half g_h1h[R_ROIS * DDIM];
__device__ __half g_h1l[R_ROIS * DDIM];
__device__ float g_h2[R_ROIS * DDIM];
__device__ float g_hpart[8 * R_ROIS * 48];
__device__ float g_xc[R_ROIS * NCLS];
__device__ float g_xd[R_ROIS * NCLS];
__device__ float g_colmax[NCLS];
__device__ float g_colsum[NCLS];

// ---------------------------------------------------------------------------
// Helpers
// ---------------------------------------------------------------------------
__device__ __forceinline__ uint32_t smem_u32(const void* p) {
    uint32_t a;
    asm("{ .reg .u64 t; cvta.to.shared.u64 t, %1; cvt.u32.u64 %0, t; }" : "=r"(a) : "l"(p));
    return a;
}

// fp16 hi/lo split: hi = rn(v), lo = rn(v - hi). hi+lo captures v to ~2^-22.
__device__ __forceinline__ void split2h(float v, __half& h, __half& l) {
    h = __float2half_rn(v);
    l = __float2half_rn(v - __half2float(h));
}

// swizzled byte offset inside a [rows x 64 fp16] (128 B/row) tile
__device__ __forceinline__ uint32_t swz(int r, int g) {
    return (uint32_t)(r >> 3) * 1024u + (uint32_t)(r & 7) * 128u
         + (uint32_t)((g ^ (r & 7)) << 4);
}

#define CP_ASYNC16(dst, src) \
    asm volatile("cp.async.cg.shared.global [%0], [%1], 16;" :: "r"(dst), "l"(src))
#define CP_COMMIT() asm volatile("cp.async.commit_group;" ::: "memory")
#define CP_WAIT1()  asm volatile("cp.async.wait_group 1;" ::: "memory")

#define LDSM_X4(r0, r1, r2, r3, addr) \
    asm volatile("ldmatrix.sync.aligned.m8n8.x4.shared.b16 {%0,%1,%2,%3}, [%4];" \
                 : "=r"(r0), "=r"(r1), "=r"(r2), "=r"(r3) : "r"(addr))

#define MMA_F16(c, a0, a1, a2, a3, b0, b1) \
    asm volatile("mma.sync.aligned.m16n8k16.row.col.f32.f16.f16.f32 " \
                 "{%0,%1,%2,%3}, {%4,%5,%6,%7}, {%8,%9}, {%0,%1,%2,%3};" \
                 : "+f"((c)[0]), "+f"((c)[1]), "+f"((c)[2]), "+f"((c)[3]) \
                 : "r"(a0), "r"(a1), "r"(a2), "r"(a3), "r"(b0), "r"(b1))

// ---------------------------------------------------------------------------
// SPP pass 1: horizontal 7-max
// ---------------------------------------------------------------------------
__global__ __launch_bounds__(256) void hmax_kernel(const float* __restrict__ x) {
    int row = blockIdx.x * 4 + (threadIdx.x >> 6);      // c*64 + y
    int xp = threadIdx.x & 63;
    if (xp >= NORI) return;
    const float* src = x + (size_t)row * HWDIM + xp;
    float m = src[0];
#pragma unroll
    for (int d = 1; d < 7; d++) m = fmaxf(m, src[d]);
    g_hmax[(size_t)row * HWDIM + xp] = m;
}

// ---------------------------------------------------------------------------
// SPP pass 2: vertical 7-max + transpose to [y'][x'][c]
// ---------------------------------------------------------------------------
__global__ __launch_bounds__(256) void vmax_kernel() {
    int yp = blockIdx.x;
    int c = blockIdx.y * 4 + threadIdx.y;
    int xp = threadIdx.x;
    if (xp >= NORI) return;
    const float* src = g_hmax + (size_t)c * HWDIM * HWDIM + (size_t)yp * HWDIM + xp;
    float m = src[0];
#pragma unroll
    for (int d = 1; d < 7; d++) m = fmaxf(m, src[d * HWDIM]);
    g_vmax[((size_t)yp * NORI + xp) * CCH + c] = m;
}

// ---------------------------------------------------------------------------
// SPP gather: per ROI, y[r, c*4 + q] from g_vmax; write fp16 hi/lo
// ---------------------------------------------------------------------------
__global__ __launch_bounds__(256) void spp_gather_kernel(const int* __restrict__ ssw) {
    __shared__ float ys[KHALF];
    int r = blockIdx.x;
    int y0 = ssw[r * 4 + 0];
    int x0 = ssw[r * 4 + 1];
    int t = threadIdx.x;
#pragma unroll
    for (int q = 0; q < 4; q++) {
        int i = q >> 1, j = q & 1;
        const float* src = g_vmax + ((size_t)(y0 + 7 * i) * NORI + (x0 + 7 * j)) * CCH;
        for (int c0 = 0; c0 < CCH; c0 += 256) {
            int c = c0 + t;
            ys[c * 4 + q] = src[c];
        }
    }
    __syncthreads();
    int k0 = t * 8;
    __half hv[8], lv[8];
#pragma unroll
    for (int u = 0; u < 8; u++) split2h(ys[k0 + u], hv[u], lv[u]);
    *reinterpret_cast<uint4*>(&g_yh[(size_t)r * KHALF + k0]) = *reinterpret_cast<uint4*>(hv);
    *reinterpret_cast<uint4*>(&g_yl[(size_t)r * KHALF + k0]) = *reinterpret_cast<uint4*>(lv);
}

// ---------------------------------------------------------------------------
// Weight fold + fp16 conversion (hi only; B-side is single-rounded fp16)
// ---------------------------------------------------------------------------
__global__ __launch_bounds__(256) void wsum_h_kernel(const float* __restrict__ w6) {
    int t = blockIdx.x * blockDim.x + threadIdx.x;
    const int NQ = DDIM * KHALF / 4;
    if (t >= NQ) return;
    int e = t / (KHALF / 4);
    int kq = t - e * (KHALF / 4);
    float4 av = reinterpret_cast<const float4*>(w6 + (size_t)e * DDIM)[kq];
    float4 bv = reinterpret_cast<const float4*>(w6 + (size_t)e * DDIM + KHALF)[kq];
    __half hv[4];
    hv[0] = __float2half_rn(av.x + bv.x);
    hv[1] = __float2half_rn(av.y + bv.y);
    hv[2] = __float2half_rn(av.z + bv.z);
    hv[3] = __float2half_rn(av.w + bv.w);
    *reinterpret_cast<uint2*>(&g_w6h[(size_t)e * KHALF + kq * 4]) = *reinterpret_cast<uint2*>(hv);
}

__global__ __launch_bounds__(256) void w7_h_kernel(const float* __restrict__ w7) {
    int t = blockIdx.x * blockDim.x + threadIdx.x;
    const int NQ = DDIM * DDIM / 4;
    if (t >= NQ) return;
    float4 v = reinterpret_cast<const float4*>(w7)[t];
    __half hv[4];
    hv[0] = __float2half_rn(v.x);
    hv[1] = __float2half_rn(v.y);
    hv[2] = __float2half_rn(v.z);
    hv[3] = __float2half_rn(v.w);
    *reinterpret_cast<uint2*>(&g_w7h[(size_t)t * 4]) = *reinterpret_cast<uint2*>(hv);
}

// ---------------------------------------------------------------------------
// fp16x2 GEMM via mma.sync: C = relu(bias + A·B^T), A = Ah+Al (fp16 pair),
// B = Bh (fp16). acc = Ah·Bh + Al·Bh  (= exact-A x fp16-B).
// CTA tile 256(M) x 128(N), K-chunk 64. 512 threads, warp tile 64x32.
// Stage: Ah 32KB + Al 32KB + Bh 16KB = 80KB; 2-stage double buffer.
// mode 0: fp32 out; mode 1: fp16 hi/lo out.
// ---------------------------------------------------------------------------
#define STAGE_B 81920
#define GEMM_SMEM (2 * STAGE_B)

__device__ __forceinline__ void load_stage(
    const __half* __restrict__ Ah, const __half* __restrict__ Al,
    const __half* __restrict__ Bh,
    int Kb, int bm0, int bn0, int k0, uint32_t sbase, int tid) {
#pragma unroll
    for (int it = 0; it < 10; it++) {
        int f = tid + it * 512;            // 0..5119 uint4 slots
        const __half* src;
        uint32_t dst;
        if (f < 2048) {
            int r = f >> 3, g = f & 7;
            src = Ah + (size_t)(bm0 + r) * Kb + k0 + g * 8;
            dst = sbase + swz(r, g);
        } else if (f < 4096) {
            int fl = f - 2048;
            int r = fl >> 3, g = fl & 7;
            src = Al + (size_t)(bm0 + r) * Kb + k0 + g * 8;
            dst = sbase + 32768u + swz(r, g);
        } else {
            int fl = f - 4096;
            int r = fl >> 3, g = fl & 7;
            src = Bh + (size_t)(bn0 + r) * Kb + k0 + g * 8;
            dst = sbase + 65536u + swz(r, g);
        }
        CP_ASYNC16(dst, src);
    }
}

__global__ __launch_bounds__(512, 1) void gemm_mma(
    const __half* __restrict__ Ah, const __half* __restrict__ Al,
    const __half* __restrict__ Bh,
    const float* __restrict__ bias, int Kb, int mode,
    float* __restrict__ Cf, __half* __restrict__ Ch, __half* __restrict__ Cl) {
    extern __shared__ __align__(128) char smp[];
    uint32_t s0 = smem_u32(smp);

    int tid = threadIdx.x;
    int wid = tid >> 5;
    int lane = tid & 31;
    int wm = wid & 3;          // warp row: 64 M-rows each
    int wn = wid >> 2;         // warp col: 32 N-cols each
    int bm0 = blockIdx.y * 256;
    int bn0 = blockIdx.x * 128;

    int lr = lane & 7;
    int a_add8 = (lane >> 3) & 1;
    int a_gsel = lane >> 4;
    int b_add8 = lane >> 4;
    int b_gsel = (lane >> 3) & 1;

    uint32_t aoff[4], boff[2];
#pragma unroll
    for (int mf = 0; mf < 4; mf++)
        aoff[mf] = (uint32_t)(wm * 8 + mf * 2 + a_add8) * 1024u + (uint32_t)lr * 128u;
#pragma unroll
    for (int nf2 = 0; nf2 < 2; nf2++)
        boff[nf2] = (uint32_t)(wn * 4 + nf2 * 2 + b_add8) * 1024u + (uint32_t)lr * 128u;

    float acc[4][4][4];
#pragma unroll
    for (int i = 0; i < 4; i++)
#pragma unroll
        for (int j = 0; j < 4; j++)
#pragma unroll
            for (int q = 0; q < 4; q++) acc[i][j][q] = 0.f;

    int nch = Kb >> 6;

    load_stage(Ah, Al, Bh, Kb, bm0, bn0, 0, s0, tid);
    CP_COMMIT();
    load_stage(Ah, Al, Bh, Kb, bm0, bn0, 64, s0 + STAGE_B, tid);
    CP_COMMIT();

    for (int kb = 0; kb < nch; kb++) {
        CP_WAIT1();
        __syncthreads();

        uint32_t abase = s0 + (kb & 1) * STAGE_B;
        uint32_t albase = abase + 32768u;
        uint32_t bbase = abase + 65536u;

#pragma unroll
        for (int ks = 0; ks < 4; ks++) {
            uint32_t b[2][4];
#pragma unroll
            for (int nf2 = 0; nf2 < 2; nf2++) {
                uint32_t addr = bbase + boff[nf2] + (uint32_t)(((2 * ks + b_gsel) ^ lr) << 4);
                LDSM_X4(b[nf2][0], b[nf2][1], b[nf2][2], b[nf2][3], addr);
            }
            uint32_t a[4][4];
#pragma unroll
            for (int mf = 0; mf < 4; mf++) {
                uint32_t addr = abase + aoff[mf] + (uint32_t)(((2 * ks + a_gsel) ^ lr) << 4);
                LDSM_X4(a[mf][0], a[mf][1], a[mf][2], a[mf][3], addr);
            }
#pragma unroll
            for (int mf = 0; mf < 4; mf++)
#pragma unroll
                for (int nf = 0; nf < 4; nf++) {
                    uint32_t b0 = b[nf >> 1][(nf & 1) * 2];
                    uint32_t b1 = b[nf >> 1][(nf & 1) * 2 + 1];
                    MMA_F16(acc[mf][nf], a[mf][0], a[mf][1], a[mf][2], a[mf][3], b0, b1);
                }
            // residual pass: Al x Bh
#pragma unroll
            for (int mf = 0; mf < 4; mf++) {
                uint32_t addr = albase + aoff[mf] + (uint32_t)(((2 * ks + a_gsel) ^ lr) << 4);
                LDSM_X4(a[mf][0], a[mf][1], a[mf][2], a[mf][3], addr);
            }
#pragma unroll
            for (int mf = 0; mf < 4; mf++)
#pragma unroll
                for (int nf = 0; nf < 4; nf++) {
                    uint32_t b0 = b[nf >> 1][(nf & 1) * 2];
                    uint32_t b1 = b[nf >> 1][(nf & 1) * 2 + 1];
                    MMA_F16(acc[mf][nf], a[mf][0], a[mf][1], a[mf][2], a[mf][3], b0, b1);
                }
        }

        __syncthreads();
        int nk = kb + 2;
        if (nk < nch) {
            load_stage(Ah, Al, Bh, Kb, bm0, bn0, nk * 64, s0 + (kb & 1) * STAGE_B, tid);
            CP_COMMIT();
        }
    }

    int gid = lane >> 2, tig = lane & 3;
#pragma unroll
    for (int mf = 0; mf < 4; mf++) {
#pragma unroll
        for (int nf = 0; nf < 4; nf++) {
            int row0 = bm0 + wm * 64 + mf * 16 + gid;
            int col = bn0 + wn * 32 + nf * 8 + tig * 2;
            float bx = __ldg(&bias[col]);
            float by = __ldg(&bias[col + 1]);
            float v00 = fmaxf(acc[mf][nf][0] + bx, 0.f);
            float v01 = fmaxf(acc[mf][nf][1] + by, 0.f);
            float v10 = fmaxf(acc[mf][nf][2] + bx, 0.f);
            float v11 = fmaxf(acc[mf][nf][3] + by, 0.f);
            if (mode == 0) {
                *reinterpret_cast<float2*>(&Cf[(size_t)row0 * DDIM + col]) = make_float2(v00, v01);
                *reinterpret_cast<float2*>(&Cf[(size_t)(row0 + 8) * DDIM + col]) = make_float2(v10, v11);
            } else {
                __half h0, l0, h1, l1;
                split2h(v00, h0, l0); split2h(v01, h1, l1);
                __half2 hp = __halves2half2(h0, h1);
                __half2 lp = __halves2half2(l0, l1);
                *reinterpret_cast<__half2*>(&Ch[(size_t)row0 * DDIM + col]) = hp;
                *reinterpret_cast<__half2*>(&Cl[(size_t)row0 * DDIM + col]) = lp;
                split2h(v10, h0, l0); split2h(v11, h1, l1);
                hp = __halves2half2(h0, h1);
                lp = __halves2half2(l0, l1);
                *reinterpret_cast<__half2*>(&Ch[(size_t)(row0 + 8) * DDIM + col]) = hp;
                *reinterpret_cast<__half2*>(&Cl[(size_t)(row0 + 8) * DDIM + col]) = lp;
            }
        }
    }
}

// ---------------------------------------------------------------------------
// Heads split-K GEMM
// ---------------------------------------------------------------------------
__global__ __launch_bounds__(256) void heads_partial(const float* __restrict__ w8c,
                                                     const float* __restrict__ w8d) {
    __shared__ float As[32][132];
    __shared__ float Bs[32][48];
    int r0 = blockIdx.x * 128;
    int ks = blockIdx.y;
    int k0 = ks * 512;
    int t = threadIdx.x;
    int ty = t >> 3, tx = t & 7;

    float acc[4][6];
#pragma unroll
    for (int i = 0; i < 4; i++)
#pragma unroll
        for (int j = 0; j < 6; j++) acc[i][j] = 0.f;

    for (int kc = 0; kc < 512; kc += 32) {
        for (int f = t; f < 1024; f += 256) {
            int r = f >> 3, q = f & 7;
            float4 v = *reinterpret_cast<const float4*>(&g_h2[(size_t)(r0 + r) * DDIM + k0 + kc + q * 4]);
            As[q * 4 + 0][r] = v.x; As[q * 4 + 1][r] = v.y;
            As[q * 4 + 2][r] = v.z; As[q * 4 + 3][r] = v.w;
        }
        for (int f = t; f < 336; f += 256) {
            int c = f >> 3, q = f & 7;
            const float* wr = (c < 21) ? (w8c + (size_t)c * DDIM) : (w8d + (size_t)(c - 21) * DDIM);
            float4 v = *reinterpret_cast<const float4*>(wr + k0 + kc + q * 4);
            Bs[q * 4 + 0][c] = v.x; Bs[q * 4 + 1][c] = v.y;
            Bs[q * 4 + 2][c] = v.z; Bs[q * 4 + 3][c] = v.w;
        }
        __syncthreads();
#pragma unroll
        for (int kk = 0; kk < 32; kk++) {
            float a[4], b[6];
#pragma unroll
            for (int i = 0; i < 4; i++) a[i] = As[kk][ty * 4 + i];
#pragma unroll
            for (int j = 0; j < 6; j++) b[j] = Bs[kk][tx * 6 + j];
#pragma unroll
            for (int i = 0; i < 4; i++)
#pragma unroll
                for (int j = 0; j < 6; j++) acc[i][j] = fmaf(a[i], b[j], acc[i][j]);
        }
        __syncthreads();
    }
#pragma unroll
    for (int i = 0; i < 4; i++) {
        int r = r0 + ty * 4 + i;
#pragma unroll
        for (int j = 0; j < 6; j++) {
            g_hpart[(size_t)ks * R_ROIS * 48 + (size_t)r * 48 + tx * 6 + j] = acc[i][j];
        }
    }
}

__global__ __launch_bounds__(256) void heads_reduce(const float* __restrict__ b8c,
                                                    const float* __restrict__ b8d) {
    int i = blockIdx.x * 256 + threadIdx.x;
    if (i >= R_ROIS * 42) return;
    int r = i / 42, c = i - r * 42;
    float s = 0.f;
#pragma unroll
    for (int ks = 0; ks < 8; ks++) s += g_hpart[(size_t)ks * R_ROIS * 48 + (size_t)r * 48 + c];
    if (c < 21) g_xc[r * NCLS + c] = fmaxf(s + b8c[c], 0.f);
    else        g_xd[r * NCLS + (c - 21)] = fmaxf(s + b8d[c - 21], 0.f);
}

// ---------------------------------------------------------------------------
// Softmax epilogue
// ---------------------------------------------------------------------------
__global__ __launch_bounds__(256) void colstats_kernel() {
    __shared__ float red[256];
    int c = blockIdx.x;
    int t = threadIdx.x;
    float m = -INFINITY;
    for (int r = t; r < R_ROIS; r += 256) m = fmaxf(m, g_xd[r * NCLS + c]);
    red[t] = m;
    __syncthreads();
    for (int s = 128; s; s >>= 1) {
        if (t < s) red[t] = fmaxf(red[t], red[t + s]);
        __syncthreads();
    }
    float cm = red[0];
    __syncthreads();
    float s2 = 0.f;
    for (int r = t; r < R_ROIS; r += 256) s2 += expf(g_xd[r * NCLS + c] - cm);
    red[t] = s2;
    __syncthreads();
    for (int s = 128; s; s >>= 1) {
        if (t < s) red[t] += red[t + s];
        __syncthreads();
    }
    if (t == 0) { g_colmax[c] = cm; g_colsum[c] = red[0]; }
}

__global__ __launch_bounds__(256) void finalize_kernel(float* __restrict__ out) {
    int warp = threadIdx.x >> 5;
    int lane = threadIdx.x & 31;
    int r = blockIdx.x * 8 + warp;
    if (r >= R_ROIS) return;

    float v = (lane < NCLS) ? g_xc[r * NCLS + lane] : -INFINITY;
    float m = v;
#pragma unroll
    for (int off = 16; off; off >>= 1) m = fmaxf(m, __shfl_xor_sync(0xFFFFFFFFu, m, off));
    float e = (lane < NCLS) ? expf(v - m) : 0.f;
    float s = e;
#pragma unroll
    for (int off = 16; off; off >>= 1) s += __shfl_xor_sync(0xFFFFFFFFu, s, off);

    if (lane < NCLS) {
        float dr = e / s;
        float smd = expf(g_xd[r * NCLS + lane] - g_colmax[lane]) / g_colsum[lane];
        out[OUT_DM + r * NCLS + lane] = dr * smd;
        out[OUT_DR + r * NCLS + lane] = dr;
    }
}

__global__ __launch_bounds__(256) void score_kernel(const float* __restrict__ dm,
                                                    float* __restrict__ score) {
    __shared__ float red[256];
    int c = blockIdx.x;
    int t = threadIdx.x;
    float s = 0.f;
    for (int r = t; r < R_ROIS; r += 256) s += dm[r * NCLS + c];
    red[t] = s;
    __syncthreads();
    for (int st = 128; st; st >>= 1) {
        if (t < st) red[t] += red[t + st];
        __syncthreads();
    }
    if (t == 0) score[c] = red[0];
}

// ---------------------------------------------------------------------------
// Launch
// ---------------------------------------------------------------------------
extern "C" void kernel_launch(void* const* d_in, const int* in_sizes, int n_in,
                              void* d_out, int out_size) {
    const float* x   = (const float*)d_in[0];
    const float* w6  = (const float*)d_in[1];
    const float* b6  = (const float*)d_in[2];
    const float* w7  = (const float*)d_in[3];
    const float* b7  = (const float*)d_in[4];
    const float* w8c = (const float*)d_in[5];
    const float* b8c = (const float*)d_in[6];
    const float* w8d = (const float*)d_in[7];
    const float* b8d = (const float*)d_in[8];
    const int*   ssw = (const int*)d_in[9];
    float* out = (float*)d_out;

    __half *p_yh, *p_yl, *p_w6h, *p_w7h, *p_h1h, *p_h1l;
    float *p_h2;
    cudaGetSymbolAddress((void**)&p_yh, g_yh);
    cudaGetSymbolAddress((void**)&p_yl, g_yl);
    cudaGetSymbolAddress((void**)&p_w6h, g_w6h);
    cudaGetSymbolAddress((void**)&p_w7h, g_w7h);
    cudaGetSymbolAddress((void**)&p_h1h, g_h1h);
    cudaGetSymbolAddress((void**)&p_h1l, g_h1l);
    cudaGetSymbolAddress((void**)&p_h2, g_h2);

    cudaFuncSetAttribute(gemm_mma, cudaFuncAttributeMaxDynamicSharedMemorySize, GEMM_SMEM);

    // 1) SPP: sliding 7x7 max + per-ROI gather
    hmax_kernel<<<CCH * HWDIM / 4, 256>>>(x);
    {
        dim3 grid(NORI, CCH / 4);
        dim3 blk(64, 4);
        vmax_kernel<<<grid, blk>>>();
    }
    spp_gather_kernel<<<R_ROIS, 256>>>(ssw);

    // 2) fold + convert weights to fp16 (hi only)
    wsum_h_kernel<<<(DDIM * KHALF / 4 + 255) / 256, 256>>>(w6);
    w7_h_kernel<<<(DDIM * DDIM / 4 + 255) / 256, 256>>>(w7);

    // 3) FC6 (fp16x2): h1 = relu(y·wsum6^T + b6) -> fp16 hi/lo
    {
        dim3 grid(DDIM / 128, R_ROIS / 256);
        gemm_mma<<<grid, 512, GEMM_SMEM>>>(p_yh, p_yl, p_w6h, b6, KHALF, 1,
                                           nullptr, p_h1h, p_h1l);
    }

    // 4) FC7: h2 = relu(h1·w7^T + b7) -> fp32
    {
        dim3 grid(DDIM / 128, R_ROIS / 256);
        gemm_mma<<<grid, 512, GEMM_SMEM>>>(p_h1h, p_h1l, p_w7h, b7, DDIM, 0,
                                           p_h2, nullptr, nullptr);
    }

    // 5) heads
    {
        dim3 grid(R_ROIS / 128, 8);
        heads_partial<<<grid, 256>>>(w8c, w8d);
        heads_reduce<<<(R_ROIS * 42 + 255) / 256, 256>>>(b8c, b8d);
    }

    // 6) softmax stats + finalize + score
    colstats_kernel<<<NCLS, 256>>>();
    finalize_kernel<<<R_ROIS / 8, 256>>>(out);
    score_kernel<<<NCLS, 256>>>(out + OUT_DM, out + OUT_SC);
}

// round 6
// speedup vs baseline: 4.3527x; 1.0544x over previous
#include <cuda_runtime.h>
#include <cuda_fp16.h>
#include <math.h>
#include <stdint.h>

// ---------------------------------------------------------------------------
// Problem constants
// ---------------------------------------------------------------------------
#define R_ROIS 2048
#define CCH    512
#define HWDIM  64
#define DDIM   4096
#define NCLS   21
#define KHALF  2048
#define NORI   58            // valid 7x7-window origins per axis (0..57)

#define OUT_DM 0
#define OUT_DR (R_ROIS * NCLS)
#define OUT_SC (2 * R_ROIS * NCLS)

// ---------------------------------------------------------------------------
// Scratch (device globals)
// ---------------------------------------------------------------------------
__device__ float g_hmax[CCH * HWDIM * HWDIM];
__device__ float g_vmax[NORI * NORI * CCH];
__device__ __half g_yh[R_ROIS * KHALF];
__device__ __half g_yl[R_ROIS * KHALF];
__device__ __half g_w6h[DDIM * KHALF];
__device__ __half g_w7h[DDIM * DDIM];
__device__ __half g_h1h[R_ROIS * DDIM];
__device__ __half g_h1l[R_ROIS * DDIM];
__device__ float g_h2[R_ROIS * DDIM];
__device__ float g_hpart[8 * R_ROIS * 48];
__device__ float g_xc[R_ROIS * NCLS];
__device__ float g_xd[R_ROIS * NCLS];
__device__ float g_colmax[NCLS];
__device__ float g_colsum[NCLS];

// ---------------------------------------------------------------------------
// Helpers
// ---------------------------------------------------------------------------
__device__ __forceinline__ uint32_t smem_u32(const void* p) {
    uint32_t a;
    asm("{ .reg .u64 t; cvta.to.shared.u64 t, %1; cvt.u32.u64 %0, t; }" : "=r"(a) : "l"(p));
    return a;
}

__device__ __forceinline__ void split2h(float v, __half& h, __half& l) {
    h = __float2half_rn(v);
    l = __float2half_rn(v - __half2float(h));
}

// swizzled byte offset inside a [rows x 64 fp16] (128 B/row) tile
__device__ __forceinline__ uint32_t swz(int r, int g) {
    return (uint32_t)(r >> 3) * 1024u + (uint32_t)(r & 7) * 128u
         + (uint32_t)((g ^ (r & 7)) << 4);
}

#define CP_ASYNC16(dst, src) \
    asm volatile("cp.async.cg.shared.global [%0], [%1], 16;" :: "r"(dst), "l"(src))
#define CP_COMMIT() asm volatile("cp.async.commit_group;" ::: "memory")
#define CP_WAIT1()  asm volatile("cp.async.wait_group 1;" ::: "memory")

#define LDSM_X4(r0, r1, r2, r3, addr) \
    asm volatile("ldmatrix.sync.aligned.m8n8.x4.shared.b16 {%0,%1,%2,%3}, [%4];" \
                 : "=r"(r0), "=r"(r1), "=r"(r2), "=r"(r3) : "r"(addr))

#define MMA_F16(c, a0, a1, a2, a3, b0, b1) \
    asm volatile("mma.sync.aligned.m16n8k16.row.col.f32.f16.f16.f32 " \
                 "{%0,%1,%2,%3}, {%4,%5,%6,%7}, {%8,%9}, {%0,%1,%2,%3};" \
                 : "+f"((c)[0]), "+f"((c)[1]), "+f"((c)[2]), "+f"((c)[3]) \
                 : "r"(a0), "r"(a1), "r"(a2), "r"(a3), "r"(b0), "r"(b1))

// ---------------------------------------------------------------------------
// SPP pass 1: horizontal 7-max
// ---------------------------------------------------------------------------
__global__ __launch_bounds__(256) void hmax_kernel(const float* __restrict__ x) {
    int row = blockIdx.x * 4 + (threadIdx.x >> 6);
    int xp = threadIdx.x & 63;
    if (xp >= NORI) return;
    const float* src = x + (size_t)row * HWDIM + xp;
    float m = src[0];
#pragma unroll
    for (int d = 1; d < 7; d++) m = fmaxf(m, src[d]);
    g_hmax[(size_t)row * HWDIM + xp] = m;
}

// ---------------------------------------------------------------------------
// SPP pass 2: vertical 7-max + transpose to [y'][x'][c]
// ---------------------------------------------------------------------------
__global__ __launch_bounds__(256) void vmax_kernel() {
    int yp = blockIdx.x;
    int c = blockIdx.y * 4 + threadIdx.y;
    int xp = threadIdx.x;
    if (xp >= NORI) return;
    const float* src = g_hmax + (size_t)c * HWDIM * HWDIM + (size_t)yp * HWDIM + xp;
    float m = src[0];
#pragma unroll
    for (int d = 1; d < 7; d++) m = fmaxf(m, src[d * HWDIM]);
    g_vmax[((size_t)yp * NORI + xp) * CCH + c] = m;
}

// ---------------------------------------------------------------------------
// SPP gather: per ROI, y[r, c*4 + q] from g_vmax; write fp16 hi/lo
// ---------------------------------------------------------------------------
__global__ __launch_bounds__(256) void spp_gather_kernel(const int* __restrict__ ssw) {
    __shared__ float ys[KHALF];
    int r = blockIdx.x;
    int y0 = ssw[r * 4 + 0];
    int x0 = ssw[r * 4 + 1];
    int t = threadIdx.x;
#pragma unroll
    for (int q = 0; q < 4; q++) {
        int i = q >> 1, j = q & 1;
        const float* src = g_vmax + ((size_t)(y0 + 7 * i) * NORI + (x0 + 7 * j)) * CCH;
        for (int c0 = 0; c0 < CCH; c0 += 256) {
            int c = c0 + t;
            ys[c * 4 + q] = src[c];
        }
    }
    __syncthreads();
    int k0 = t * 8;
    __half hv[8], lv[8];
#pragma unroll
    for (int u = 0; u < 8; u++) split2h(ys[k0 + u], hv[u], lv[u]);
    *reinterpret_cast<uint4*>(&g_yh[(size_t)r * KHALF + k0]) = *reinterpret_cast<uint4*>(hv);
    *reinterpret_cast<uint4*>(&g_yl[(size_t)r * KHALF + k0]) = *reinterpret_cast<uint4*>(lv);
}

// ---------------------------------------------------------------------------
// Weight fold + fp16 conversion (hi only; B-side is single-rounded fp16)
// ---------------------------------------------------------------------------
__global__ __launch_bounds__(256) void wsum_h_kernel(const float* __restrict__ w6) {
    int t = blockIdx.x * blockDim.x + threadIdx.x;
    const int NQ = DDIM * KHALF / 4;
    if (t >= NQ) return;
    int e = t / (KHALF / 4);
    int kq = t - e * (KHALF / 4);
    float4 av = reinterpret_cast<const float4*>(w6 + (size_t)e * DDIM)[kq];
    float4 bv = reinterpret_cast<const float4*>(w6 + (size_t)e * DDIM + KHALF)[kq];
    __half hv[4];
    hv[0] = __float2half_rn(av.x + bv.x);
    hv[1] = __float2half_rn(av.y + bv.y);
    hv[2] = __float2half_rn(av.z + bv.z);
    hv[3] = __float2half_rn(av.w + bv.w);
    *reinterpret_cast<uint2*>(&g_w6h[(size_t)e * KHALF + kq * 4]) = *reinterpret_cast<uint2*>(hv);
}

__global__ __launch_bounds__(256) void w7_h_kernel(const float* __restrict__ w7) {
    int t = blockIdx.x * blockDim.x + threadIdx.x;
    const int NQ = DDIM * DDIM / 4;
    if (t >= NQ) return;
    float4 v = reinterpret_cast<const float4*>(w7)[t];
    __half hv[4];
    hv[0] = __float2half_rn(v.x);
    hv[1] = __float2half_rn(v.y);
    hv[2] = __float2half_rn(v.z);
    hv[3] = __float2half_rn(v.w);
    *reinterpret_cast<uint2*>(&g_w7h[(size_t)t * 4]) = *reinterpret_cast<uint2*>(hv);
}

// ---------------------------------------------------------------------------
// fp16x2 GEMM via mma.sync: C = relu(bias + A·B^T), A = Ah+Al (fp16 pair),
// B = Bh (fp16). acc = Ah·Bh + Al·Bh.
// CTA tile 128x128, K-chunk 64. 128 threads (4 warps), warp tile 64x64.
// Stage: Ah 16KB + Al 16KB + Bh 16KB = 48KB; 2-stage -> 96KB, 2 CTAs/SM.
// mode 0: fp32 out; mode 1: fp16 hi/lo out.
// ---------------------------------------------------------------------------
#define STAGE_B 49152
#define GEMM_SMEM (2 * STAGE_B)

__device__ __forceinline__ void load_stage(
    const __half* __restrict__ Ah, const __half* __restrict__ Al,
    const __half* __restrict__ Bh,
    int Kb, int bm0, int bn0, int k0, uint32_t sbase, int tid) {
#pragma unroll
    for (int it = 0; it < 24; it++) {
        int f = tid + it * 128;            // 0..3071 uint4 slots
        int sel = f >> 10;                 // 0:Ah 1:Al 2:Bh
        int fl = f & 1023;
        int r = fl >> 3, g = fl & 7;
        const __half* src;
        if (sel == 0)      src = Ah + (size_t)(bm0 + r) * Kb + k0 + g * 8;
        else if (sel == 1) src = Al + (size_t)(bm0 + r) * Kb + k0 + g * 8;
        else               src = Bh + (size_t)(bn0 + r) * Kb + k0 + g * 8;
        uint32_t dst = sbase + (uint32_t)sel * 16384u + swz(r, g);
        CP_ASYNC16(dst, src);
    }
}

__global__ __launch_bounds__(128, 2) void gemm_mma(
    const __half* __restrict__ Ah, const __half* __restrict__ Al,
    const __half* __restrict__ Bh,
    const float* __restrict__ bias, int Kb, int mode,
    float* __restrict__ Cf, __half* __restrict__ Ch, __half* __restrict__ Cl) {
    extern __shared__ __align__(128) char smp[];
    uint32_t s0 = smem_u32(smp);

    int tid = threadIdx.x;
    int wid = tid >> 5;
    int lane = tid & 31;
    int wm = wid & 1;          // warp row: 64 M-rows
    int wn = wid >> 1;         // warp col: 64 N-cols
    int bm0 = blockIdx.y * 128;
    int bn0 = blockIdx.x * 128;

    int lr = lane & 7;
    int a_add8 = (lane >> 3) & 1;
    int a_gsel = lane >> 4;
    int b_add8 = lane >> 4;
    int b_gsel = (lane >> 3) & 1;

    uint32_t aoff[4], boff[4];
#pragma unroll
    for (int mf = 0; mf < 4; mf++)
        aoff[mf] = (uint32_t)(wm * 8 + mf * 2 + a_add8) * 1024u + (uint32_t)lr * 128u;
#pragma unroll
    for (int nf2 = 0; nf2 < 4; nf2++)
        boff[nf2] = (uint32_t)(wn * 8 + nf2 * 2 + b_add8) * 1024u + (uint32_t)lr * 128u;

    float acc[4][8][4];
#pragma unroll
    for (int i = 0; i < 4; i++)
#pragma unroll
        for (int j = 0; j < 8; j++)
#pragma unroll
            for (int q = 0; q < 4; q++) acc[i][j][q] = 0.f;

    int nch = Kb >> 6;

    load_stage(Ah, Al, Bh, Kb, bm0, bn0, 0, s0, tid);
    CP_COMMIT();
    load_stage(Ah, Al, Bh, Kb, bm0, bn0, 64, s0 + STAGE_B, tid);
    CP_COMMIT();

    for (int kb = 0; kb < nch; kb++) {
        CP_WAIT1();
        __syncthreads();

        uint32_t abase = s0 + (kb & 1) * STAGE_B;
        uint32_t albase = abase + 16384u;
        uint32_t bbase = abase + 32768u;

#pragma unroll
        for (int ks = 0; ks < 4; ks++) {
            uint32_t b[4][4];
#pragma unroll
            for (int nf2 = 0; nf2 < 4; nf2++) {
                uint32_t addr = bbase + boff[nf2] + (uint32_t)(((2 * ks + b_gsel) ^ lr) << 4);
                LDSM_X4(b[nf2][0], b[nf2][1], b[nf2][2], b[nf2][3], addr);
            }
            uint32_t a[4][4];
#pragma unroll
            for (int mf = 0; mf < 4; mf++) {
                uint32_t addr = abase + aoff[mf] + (uint32_t)(((2 * ks + a_gsel) ^ lr) << 4);
                LDSM_X4(a[mf][0], a[mf][1], a[mf][2], a[mf][3], addr);
            }
#pragma unroll
            for (int mf = 0; mf < 4; mf++)
#pragma unroll
                for (int nf = 0; nf < 8; nf++) {
                    uint32_t b0 = b[nf >> 1][(nf & 1) * 2];
                    uint32_t b1 = b[nf >> 1][(nf & 1) * 2 + 1];
                    MMA_F16(acc[mf][nf], a[mf][0], a[mf][1], a[mf][2], a[mf][3], b0, b1);
                }
            // residual pass: Al x Bh (B frags reused)
#pragma unroll
            for (int mf = 0; mf < 4; mf++) {
                uint32_t addr = albase + aoff[mf] + (uint32_t)(((2 * ks + a_gsel) ^ lr) << 4);
                LDSM_X4(a[mf][0], a[mf][1], a[mf][2], a[mf][3], addr);
            }
#pragma unroll
            for (int mf = 0; mf < 4; mf++)
#pragma unroll
                for (int nf = 0; nf < 8; nf++) {
                    uint32_t b0 = b[nf >> 1][(nf & 1) * 2];
                    uint32_t b1 = b[nf >> 1][(nf & 1) * 2 + 1];
                    MMA_F16(acc[mf][nf], a[mf][0], a[mf][1], a[mf][2], a[mf][3], b0, b1);
                }
        }

        __syncthreads();
        int nk = kb + 2;
        if (nk < nch) {
            load_stage(Ah, Al, Bh, Kb, bm0, bn0, nk * 64, s0 + (kb & 1) * STAGE_B, tid);
            CP_COMMIT();
        }
    }

    int gid = lane >> 2, tig = lane & 3;
#pragma unroll
    for (int mf = 0; mf < 4; mf++) {
#pragma unroll
        for (int nf = 0; nf < 8; nf++) {
            int row0 = bm0 + wm * 64 + mf * 16 + gid;
            int col = bn0 + wn * 64 + nf * 8 + tig * 2;
            float bx = __ldg(&bias[col]);
            float by = __ldg(&bias[col + 1]);
            float v00 = fmaxf(acc[mf][nf][0] + bx, 0.f);
            float v01 = fmaxf(acc[mf][nf][1] + by, 0.f);
            float v10 = fmaxf(acc[mf][nf][2] + bx, 0.f);
            float v11 = fmaxf(acc[mf][nf][3] + by, 0.f);
            if (mode == 0) {
                *reinterpret_cast<float2*>(&Cf[(size_t)row0 * DDIM + col]) = make_float2(v00, v01);
                *reinterpret_cast<float2*>(&Cf[(size_t)(row0 + 8) * DDIM + col]) = make_float2(v10, v11);
            } else {
                __half h0, l0, h1, l1;
                split2h(v00, h0, l0); split2h(v01, h1, l1);
                *reinterpret_cast<__half2*>(&Ch[(size_t)row0 * DDIM + col]) = __halves2half2(h0, h1);
                *reinterpret_cast<__half2*>(&Cl[(size_t)row0 * DDIM + col]) = __halves2half2(l0, l1);
                split2h(v10, h0, l0); split2h(v11, h1, l1);
                *reinterpret_cast<__half2*>(&Ch[(size_t)(row0 + 8) * DDIM + col]) = __halves2half2(h0, h1);
                *reinterpret_cast<__half2*>(&Cl[(size_t)(row0 + 8) * DDIM + col]) = __halves2half2(l0, l1);
            }
        }
    }
}

// ---------------------------------------------------------------------------
// Heads split-K GEMM
// ---------------------------------------------------------------------------
__global__ __launch_bounds__(256) void heads_partial(const float* __restrict__ w8c,
                                                     const float* __restrict__ w8d) {
    __shared__ float As[32][132];
    __shared__ float Bs[32][48];
    int r0 = blockIdx.x * 128;
    int ks = blockIdx.y;
    int k0 = ks * 512;
    int t = threadIdx.x;
    int ty = t >> 3, tx = t & 7;

    float acc[4][6];
#pragma unroll
    for (int i = 0; i < 4; i++)
#pragma unroll
        for (int j = 0; j < 6; j++) acc[i][j] = 0.f;

    for (int kc = 0; kc < 512; kc += 32) {
        for (int f = t; f < 1024; f += 256) {
            int r = f >> 3, q = f & 7;
            float4 v = *reinterpret_cast<const float4*>(&g_h2[(size_t)(r0 + r) * DDIM + k0 + kc + q * 4]);
            As[q * 4 + 0][r] = v.x; As[q * 4 + 1][r] = v.y;
            As[q * 4 + 2][r] = v.z; As[q * 4 + 3][r] = v.w;
        }
        for (int f = t; f < 336; f += 256) {
            int c = f >> 3, q = f & 7;
            const float* wr = (c < 21) ? (w8c + (size_t)c * DDIM) : (w8d + (size_t)(c - 21) * DDIM);
            float4 v = *reinterpret_cast<const float4*>(wr + k0 + kc + q * 4);
            Bs[q * 4 + 0][c] = v.x; Bs[q * 4 + 1][c] = v.y;
            Bs[q * 4 + 2][c] = v.z; Bs[q * 4 + 3][c] = v.w;
        }
        __syncthreads();
#pragma unroll
        for (int kk = 0; kk < 32; kk++) {
            float a[4], b[6];
#pragma unroll
            for (int i = 0; i < 4; i++) a[i] = As[kk][ty * 4 + i];
#pragma unroll
            for (int j = 0; j < 6; j++) b[j] = Bs[kk][tx * 6 + j];
#pragma unroll
            for (int i = 0; i < 4; i++)
#pragma unroll
                for (int j = 0; j < 6; j++) acc[i][j] = fmaf(a[i], b[j], acc[i][j]);
        }
        __syncthreads();
    }
#pragma unroll
    for (int i = 0; i < 4; i++) {
        int r = r0 + ty * 4 + i;
#pragma unroll
        for (int j = 0; j < 6; j++) {
            g_hpart[(size_t)ks * R_ROIS * 48 + (size_t)r * 48 + tx * 6 + j] = acc[i][j];
        }
    }
}

__global__ __launch_bounds__(256) void heads_reduce(const float* __restrict__ b8c,
                                                    const float* __restrict__ b8d) {
    int i = blockIdx.x * 256 + threadIdx.x;
    if (i >= R_ROIS * 42) return;
    int r = i / 42, c = i - r * 42;
    float s = 0.f;
#pragma unroll
    for (int ks = 0; ks < 8; ks++) s += g_hpart[(size_t)ks * R_ROIS * 48 + (size_t)r * 48 + c];
    if (c < 21) g_xc[r * NCLS + c] = fmaxf(s + b8c[c], 0.f);
    else        g_xd[r * NCLS + (c - 21)] = fmaxf(s + b8d[c - 21], 0.f);
}

// ---------------------------------------------------------------------------
// Softmax epilogue
// ---------------------------------------------------------------------------
__global__ __launch_bounds__(256) void colstats_kernel() {
    __shared__ float red[256];
    int c = blockIdx.x;
    int t = threadIdx.x;
    float m = -INFINITY;
    for (int r = t; r < R_ROIS; r += 256) m = fmaxf(m, g_xd[r * NCLS + c]);
    red[t] = m;
    __syncthreads();
    for (int s = 128; s; s >>= 1) {
        if (t < s) red[t] = fmaxf(red[t], red[t + s]);
        __syncthreads();
    }
    float cm = red[0];
    __syncthreads();
    float s2 = 0.f;
    for (int r = t; r < R_ROIS; r += 256) s2 += expf(g_xd[r * NCLS + c] - cm);
    red[t] = s2;
    __syncthreads();
    for (int s = 128; s; s >>= 1) {
        if (t < s) red[t] += red[t + s];
        __syncthreads();
    }
    if (t == 0) { g_colmax[c] = cm; g_colsum[c] = red[0]; }
}

__global__ __launch_bounds__(256) void finalize_kernel(float* __restrict__ out) {
    int warp = threadIdx.x >> 5;
    int lane = threadIdx.x & 31;
    int r = blockIdx.x * 8 + warp;
    if (r >= R_ROIS) return;

    float v = (lane < NCLS) ? g_xc[r * NCLS + lane] : -INFINITY;
    float m = v;
#pragma unroll
    for (int off = 16; off; off >>= 1) m = fmaxf(m, __shfl_xor_sync(0xFFFFFFFFu, m, off));
    float e = (lane < NCLS) ? expf(v - m) : 0.f;
    float s = e;
#pragma unroll
    for (int off = 16; off; off >>= 1) s += __shfl_xor_sync(0xFFFFFFFFu, s, off);

    if (lane < NCLS) {
        float dr = e / s;
        float smd = expf(g_xd[r * NCLS + lane] - g_colmax[lane]) / g_colsum[lane];
        out[OUT_DM + r * NCLS + lane] = dr * smd;
        out[OUT_DR + r * NCLS + lane] = dr;
    }
}

__global__ __launch_bounds__(256) void score_kernel(const float* __restrict__ dm,
                                                    float* __restrict__ score) {
    __shared__ float red[256];
    int c = blockIdx.x;
    int t = threadIdx.x;
    float s = 0.f;
    for (int r = t; r < R_ROIS; r += 256) s += dm[r * NCLS + c];
    red[t] = s;
    __syncthreads();
    for (int st = 128; st; st >>= 1) {
        if (t < st) red[t] += red[t + st];
        __syncthreads();
    }
    if (t == 0) score[c] = red[0];
}

// ---------------------------------------------------------------------------
// Launch (prep kernels first so ncu's "-s 5 -c 1" capture lands on FC6 GEMM)
// ---------------------------------------------------------------------------
extern "C" void kernel_launch(void* const* d_in, const int* in_sizes, int n_in,
                              void* d_out, int out_size) {
    const float* x   = (const float*)d_in[0];
    const float* w6  = (const float*)d_in[1];
    const float* b6  = (const float*)d_in[2];
    const float* w7  = (const float*)d_in[3];
    const float* b7  = (const float*)d_in[4];
    const float* w8c = (const float*)d_in[5];
    const float* b8c = (const float*)d_in[6];
    const float* w8d = (const float*)d_in[7];
    const float* b8d = (const float*)d_in[8];
    const int*   ssw = (const int*)d_in[9];
    float* out = (float*)d_out;

    __half *p_yh, *p_yl, *p_w6h, *p_w7h, *p_h1h, *p_h1l;
    float *p_h2;
    cudaGetSymbolAddress((void**)&p_yh, g_yh);
    cudaGetSymbolAddress((void**)&p_yl, g_yl);
    cudaGetSymbolAddress((void**)&p_w6h, g_w6h);
    cudaGetSymbolAddress((void**)&p_w7h, g_w7h);
    cudaGetSymbolAddress((void**)&p_h1h, g_h1h);
    cudaGetSymbolAddress((void**)&p_h1l, g_h1l);
    cudaGetSymbolAddress((void**)&p_h2, g_h2);

    cudaFuncSetAttribute(gemm_mma, cudaFuncAttributeMaxDynamicSharedMemorySize, GEMM_SMEM);

    // 1) weight prep first (independent of SPP)
    wsum_h_kernel<<<(DDIM * KHALF / 4 + 255) / 256, 256>>>(w6);     // launch 1
    w7_h_kernel<<<(DDIM * DDIM / 4 + 255) / 256, 256>>>(w7);        // launch 2

    // 2) SPP
    hmax_kernel<<<CCH * HWDIM / 4, 256>>>(x);                       // launch 3
    {
        dim3 grid(NORI, CCH / 4);
        dim3 blk(64, 4);
        vmax_kernel<<<grid, blk>>>();                               // launch 4
    }
    spp_gather_kernel<<<R_ROIS, 256>>>(ssw);                        // launch 5

    // 3) FC6 (fp16x2): h1 = relu(y·wsum6^T + b6) -> fp16 hi/lo    // launch 6 (profiled)
    {
        dim3 grid(DDIM / 128, R_ROIS / 128);
        gemm_mma<<<grid, 128, GEMM_SMEM>>>(p_yh, p_yl, p_w6h, b6, KHALF, 1,
                                           nullptr, p_h1h, p_h1l);
    }

    // 4) FC7: h2 = relu(h1·w7^T + b7) -> fp32
    {
        dim3 grid(DDIM / 128, R_ROIS / 128);
        gemm_mma<<<grid, 128, GEMM_SMEM>>>(p_h1h, p_h1l, p_w7h, b7, DDIM, 0,
                                           p_h2, nullptr, nullptr);
    }

    // 5) heads
    {
        dim3 grid(R_ROIS / 128, 8);
        heads_partial<<<grid, 256>>>(w8c, w8d);
        heads_reduce<<<(R_ROIS * 42 + 255) / 256, 256>>>(b8c, b8d);
    }

    // 6) softmax stats + finalize + score
    colstats_kernel<<<NCLS, 256>>>();
    finalize_kernel<<<R_ROIS / 8, 256>>>(out);
    score_kernel<<<NCLS, 256>>>(out + OUT_DM, out + OUT_SC);
}